// round 10
// baseline (speedup 1.0000x reference)
#include <cuda_runtime.h>
#include <cuda_bf16.h>
#include <math.h>
#include <stdint.h>

// Problem constants (fixed by the dataset)
#define D_DIM   1024
#define F_DIM   2048
#define E_NUM   8
#define N_TOK   2048
#define NPAIR   4096
#define PADROWS 5120
#define MAXTILES 40
#define NS1 32            // 1024/32 K-stages, GEMM1
#define NS2 64            // 2048/32 K-stages, GEMM2
#define LDA 36            // fp32 elems per row (32 + 4 pad) -> 144B stride

#define A_BYTES  (128 * LDA * 4)          // 18432
#define B_BYTES  (64 * LDA * 4)           // 9216
#define STAGE1   (A_BYTES + 2 * B_BYTES)  // 36864
#define STAGE2   (A_BYTES + B_BYTES)      // 27648
#define SMEM1    (2 * STAGE1)             // 73728
#define SMEM2    (2 * STAGE2)             // 55296

// Scratch (device globals — no runtime allocation allowed)
__device__ float g_inner[(size_t)PADROWS * F_DIM];   // tf32-rounded fp32
__device__ int   g_pair_token[PADROWS];
__device__ float g_pair_w[PADROWS];
__device__ int   g_topi[N_TOK * 2];
__device__ float g_topw[N_TOK * 2];
__device__ int   g_counts[E_NUM];
__device__ int   g_cursor[E_NUM];
__device__ int   g_tile_e[MAXTILES];

__device__ __forceinline__ uint32_t f2tf(float f) {
    uint32_t u;
    asm("cvt.rna.tf32.f32 %0, %1;" : "=r"(u) : "f"(f));
    return u;
}
__device__ __forceinline__ uint32_t s2u(const void* p) {
    return (uint32_t)__cvta_generic_to_shared((void*)p);
}
__device__ __forceinline__ void mma_tf32(float c[4], const uint32_t a[4],
                                         const uint32_t b[2]) {
    asm volatile(
        "mma.sync.aligned.m16n8k8.row.col.f32.tf32.tf32.f32 "
        "{%0,%1,%2,%3}, {%4,%5,%6,%7}, {%8,%9}, {%0,%1,%2,%3};\n"
        : "+f"(c[0]), "+f"(c[1]), "+f"(c[2]), "+f"(c[3])
        : "r"(a[0]), "r"(a[1]), "r"(a[2]), "r"(a[3]), "r"(b[0]), "r"(b[1]));
}
__device__ __forceinline__ void ldsm4(uint32_t r[4], uint32_t addr) {
    asm volatile("ldmatrix.sync.aligned.m8n8.x4.shared.b16 {%0,%1,%2,%3}, [%4];"
                 : "=r"(r[0]), "=r"(r[1]), "=r"(r[2]), "=r"(r[3]) : "r"(addr));
}
// ldsm4 with our aoff returns {(r0-7,k0-3),(r0-7,k4-7),(r8-15,k0-3),(r8-15,k4-7)}.
// The tf32 A fragment wants {a0,a1,a2,a3}={(g4,t4),(g4+8,t4),(g4,t4+4),(g4+8,t4+4)}
// = {r0, r2, r1, r3}  -> reorder here.
__device__ __forceinline__ void ldsmA(uint32_t a[4], uint32_t addr) {
    uint32_t r[4];
    ldsm4(r, addr);
    a[0] = r[0]; a[1] = r[2]; a[2] = r[1]; a[3] = r[3];
}

// ---------------------------------------------------------------------------
// small kernels
// ---------------------------------------------------------------------------
__global__ void init_kernel(float* out, int out_size) {
    int idx = blockIdx.x * blockDim.x + threadIdx.x;
    if (idx < out_size) out[idx] = 0.f;
    if (idx < PADROWS)  g_pair_token[idx] = -1;
    if (idx < E_NUM)    g_counts[idx] = 0;
}

__global__ void router_kernel(const float* __restrict__ x,
                              const float* __restrict__ Wg) {
    int warp = threadIdx.x >> 5;
    int lane = threadIdx.x & 31;
    int n = blockIdx.x * 8 + warp;
    if (n >= N_TOK) return;
    float acc[E_NUM];
#pragma unroll
    for (int e = 0; e < E_NUM; e++) acc[e] = 0.f;
    const float* xr = x + (size_t)n * D_DIM;
    for (int d = lane; d < D_DIM; d += 32) {
        float xv = xr[d];
#pragma unroll
        for (int e = 0; e < E_NUM; e++) acc[e] += xv * Wg[d * E_NUM + e];
    }
#pragma unroll
    for (int e = 0; e < E_NUM; e++) {
#pragma unroll
        for (int off = 16; off > 0; off >>= 1)
            acc[e] += __shfl_xor_sync(0xffffffffu, acc[e], off);
    }
    if (lane == 0) {
        float m = acc[0];
#pragma unroll
        for (int e = 1; e < E_NUM; e++) m = fmaxf(m, acc[e]);
        float p[E_NUM];
#pragma unroll
        for (int e = 0; e < E_NUM; e++) p[e] = expf(acc[e] - m);
        int i1 = 0;
#pragma unroll
        for (int e = 1; e < E_NUM; e++) if (p[e] > p[i1]) i1 = e;
        int i2 = (i1 == 0) ? 1 : 0;
#pragma unroll
        for (int e = 0; e < E_NUM; e++)
            if (e != i1 && p[e] > p[i2]) i2 = e;
        float inv = 1.f / (p[i1] + p[i2]);
        g_topi[n * 2 + 0] = i1;  g_topw[n * 2 + 0] = p[i1] * inv;
        g_topi[n * 2 + 1] = i2;  g_topw[n * 2 + 1] = p[i2] * inv;
        atomicAdd(&g_counts[i1], 1);
        atomicAdd(&g_counts[i2], 1);
    }
}

__global__ void setup_kernel() {
    if (threadIdx.x != 0 || blockIdx.x != 0) return;
    int off = 0;
    int pad[E_NUM];
    for (int e = 0; e < E_NUM; e++) {
        g_cursor[e] = off;
        int p = ((g_counts[e] + 127) / 128) * 128;
        pad[e] = p;
        off += p;
    }
    int t = 0;
    for (int e = 0; e < E_NUM; e++)
        for (int r = 0; r < pad[e]; r += 128) g_tile_e[t++] = e;
    for (; t < MAXTILES; t++) g_tile_e[t] = -1;
}

__global__ void scatter_kernel() {
    int idx = blockIdx.x * blockDim.x + threadIdx.x;
    if (idx >= NPAIR) return;
    int e = g_topi[idx];
    int pos = atomicAdd(&g_cursor[e], 1);
    g_pair_token[pos] = idx >> 1;
    g_pair_w[pos] = g_topw[idx];
}

// ---------------------------------------------------------------------------
// B-tile store: cvt.rna + 4x4 shfl transpose + STS.128 (conflict-free).
// Lane (a = lane>>2, b = lane&3) loaded bv[p] = W[khb+4p+b][n cols nh+a*4..+3].
// After transpose lane holds n = nh + a*4 + b, k-run of 4 at khb+4p.
// ---------------------------------------------------------------------------
__device__ __forceinline__ void sts_B(char* sB, const float4* bv, int np,
                                      int nh, int khb, int lane) {
    int a = lane >> 2, b = lane & 3;
#pragma unroll
    for (int p = 0; p < 4; p++) {
        if (p >= np) break;
        uint32_t t[4] = { f2tf(bv[p].x), f2tf(bv[p].y), f2tf(bv[p].z), f2tf(bv[p].w) };
        uint32_t w4[4];
#pragma unroll
        for (int s = 0; s < 4; s++) {
            int j = (b - s) & 3;
            w4[j] = __shfl_sync(0xffffffffu, t[(b + s) & 3], (lane & ~3) | j);
        }
        int n = nh + a * 4 + b;
        *(uint4*)(sB + n * (LDA * 4) + (khb + p * 4) * 4) =
            make_uint4(w4[0], w4[1], w4[2], w4[3]);
    }
}

// ---------------------------------------------------------------------------
// GEMM1: inner = gelu(X@W_in + b_in) * (X@W_scale + b_scale)
// Grid (F/64, MAXTILES). 256 thr, warps: wm=warp&3 (32 rows), wn=warp>>2 (32 cols).
// ---------------------------------------------------------------------------
extern __shared__ __align__(16) char dynsmem[];

__global__ __launch_bounds__(256, 1)
void gemm1_kernel(const float* __restrict__ x,   const float* __restrict__ Win,
                  const float* __restrict__ bin, const float* __restrict__ Wsc,
                  const float* __restrict__ bsc) {
    int e = g_tile_e[blockIdx.y];
    if (e < 0) return;
    int row0 = blockIdx.y * 128;
    int n0   = blockIdx.x * 64;

    int tid = threadIdx.x;
    int lane = tid & 31, warp = tid >> 5;
    int wm = warp & 3, wn = warp >> 2;
    int g4 = lane >> 2, t4 = lane & 3;

    // A gather mapping: rows rA + 32i, fixed kv
    int rA = tid >> 3, kv = tid & 7;
    const float* xptr[4];
    bool tval[4];
#pragma unroll
    for (int i = 0; i < 4; i++) {
        int tok = g_pair_token[row0 + rA + i * 32];
        tval[i] = (tok >= 0);
        xptr[i] = x + (size_t)(tok >= 0 ? tok : 0) * D_DIM + kv * 4;
    }
    // B loader mapping: warp -> matrix (warp&1), k-half khB, n-half nhB
    int aq = lane >> 2, bq = lane & 3;
    int khB = ((warp >> 1) & 1) * 16;
    int nhB = (warp >> 2) * 32;
    const float* wsel = (warp & 1) ? Wsc : Win;
    const float* bbase = wsel + ((size_t)e * D_DIM + khB + bq) * F_DIM + n0 + nhB + aq * 4;

    // ldmatrix per-lane offset: lanes 0-7 rows 0-7 k0-3; 8-15 rows 0-7 k4-7;
    // 16-23 rows 8-15 k0-3; 24-31 rows 8-15 k4-7.
    uint32_t aoff = (uint32_t)(((lane & 7) + ((lane >> 4) & 1) * 8) * (LDA * 4)
                               + ((lane >> 3) & 1) * 16);

    float cH[2][4][4], cS[2][4][4];
#pragma unroll
    for (int mi = 0; mi < 2; mi++)
#pragma unroll
        for (int ni = 0; ni < 4; ni++)
#pragma unroll
            for (int j = 0; j < 4; j++) { cH[mi][ni][j] = 0.f; cS[mi][ni][j] = 0.f; }

    float4 av[4], bv[4];
    // prologue loads for k0 = 0
#pragma unroll
    for (int i = 0; i < 4; i++)
        av[i] = tval[i] ? *(const float4*)(xptr[i]) : make_float4(0.f, 0.f, 0.f, 0.f);
#pragma unroll
    for (int p = 0; p < 4; p++)
        bv[p] = *(const float4*)(bbase + (size_t)(p * 4) * F_DIM);

    for (int it = 0; it < NS1; it++) {
        char* sA  = dynsmem + (it & 1) * STAGE1;
        char* sB1 = sA + A_BYTES;
        char* sB2 = sB1 + B_BYTES;
        // store current stage
#pragma unroll
        for (int i = 0; i < 4; i++) {
            uint4 u = make_uint4(f2tf(av[i].x), f2tf(av[i].y), f2tf(av[i].z), f2tf(av[i].w));
            *(uint4*)(sA + (rA + i * 32) * (LDA * 4) + kv * 16) = u;
        }
        sts_B((warp & 1) ? sB2 : sB1, bv, 4, nhB, khB, lane);
        __syncthreads();
        // prefetch next stage
        if (it + 1 < NS1) {
            int k0 = (it + 1) * 32;
#pragma unroll
            for (int i = 0; i < 4; i++)
                av[i] = tval[i] ? *(const float4*)(xptr[i] + k0)
                                : make_float4(0.f, 0.f, 0.f, 0.f);
#pragma unroll
            for (int p = 0; p < 4; p++)
                bv[p] = *(const float4*)(bbase + (size_t)(k0 + p * 4) * F_DIM);
        }
        // compute
        uint32_t aA  = s2u(sA)  + (uint32_t)(wm * 32 * (LDA * 4)) + aoff;
        uint32_t aB1 = s2u(sB1) + (uint32_t)(wn * 32 * (LDA * 4)) + aoff;
        uint32_t aB2 = s2u(sB2) + (uint32_t)(wn * 32 * (LDA * 4)) + aoff;
#pragma unroll
        for (int kb = 0; kb < 4; kb++) {
            uint32_t koff = kb * 32;
            uint32_t a[2][4], f1[2][4], f2[2][4];
            ldsmA(a[0], aA + koff);
            ldsmA(a[1], aA + 16 * (LDA * 4) + koff);
            ldsm4(f1[0], aB1 + koff);
            ldsm4(f1[1], aB1 + 16 * (LDA * 4) + koff);
            ldsm4(f2[0], aB2 + koff);
            ldsm4(f2[1], aB2 + 16 * (LDA * 4) + koff);
#pragma unroll
            for (int mi = 0; mi < 2; mi++)
#pragma unroll
                for (int j = 0; j < 2; j++) {
                    mma_tf32(cH[mi][2 * j],     a[mi], &f1[j][0]);
                    mma_tf32(cH[mi][2 * j + 1], a[mi], &f1[j][2]);
                    mma_tf32(cS[mi][2 * j],     a[mi], &f2[j][0]);
                    mma_tf32(cS[mi][2 * j + 1], a[mi], &f2[j][2]);
                }
        }
        __syncthreads();
    }

    // epilogue: exact GELU gate, tf32-rounded fp32 store
#pragma unroll
    for (int mi = 0; mi < 2; mi++) {
#pragma unroll
        for (int ni = 0; ni < 4; ni++) {
            int col = n0 + wn * 32 + ni * 8 + t4 * 2;
            float bi0 = bin[e * F_DIM + col], bi1 = bin[e * F_DIM + col + 1];
            float bs0 = bsc[e * F_DIM + col], bs1 = bsc[e * F_DIM + col + 1];
#pragma unroll
            for (int h = 0; h < 2; h++) {
                int row = row0 + wm * 32 + mi * 16 + g4 + h * 8;
                float h0 = cH[mi][ni][h * 2 + 0] + bi0;
                float h1 = cH[mi][ni][h * 2 + 1] + bi1;
                float s0 = cS[mi][ni][h * 2 + 0] + bs0;
                float s1 = cS[mi][ni][h * 2 + 1] + bs1;
                float gl0 = 0.5f * h0 * (1.f + erff(h0 * 0.70710678118654752f));
                float gl1 = 0.5f * h1 * (1.f + erff(h1 * 0.70710678118654752f));
                float2 o;
                o.x = __uint_as_float(f2tf(gl0 * s0));
                o.y = __uint_as_float(f2tf(gl1 * s1));
                *(float2*)(g_inner + (size_t)row * F_DIM + col) = o;
            }
        }
    }
}

// ---------------------------------------------------------------------------
// GEMM2: y = inner @ W_out + b_out; out[token] += gate * y (atomic)
// Grid (D/64, MAXTILES)
// ---------------------------------------------------------------------------
__global__ __launch_bounds__(256, 1)
void gemm2_kernel(const float* __restrict__ Wout, const float* __restrict__ bout,
                  float* __restrict__ out) {
    int e = g_tile_e[blockIdx.y];
    if (e < 0) return;
    int row0 = blockIdx.y * 128;
    int n0   = blockIdx.x * 64;

    int tid = threadIdx.x;
    int lane = tid & 31, warp = tid >> 5;
    int wm = warp & 3, wn = warp >> 2;
    int g4 = lane >> 2, t4 = lane & 3;

    int rA = tid >> 3, kv = tid & 7;
    const float* aptr[4];
#pragma unroll
    for (int i = 0; i < 4; i++)
        aptr[i] = g_inner + (size_t)(row0 + rA + i * 32) * F_DIM + kv * 4;

    int aq = lane >> 2, bq = lane & 3;
    int khB = (warp & 3) * 8;
    int nhB = (warp >> 2) * 32;
    const float* bbase = Wout + ((size_t)e * F_DIM + khB + bq) * D_DIM + n0 + nhB + aq * 4;

    uint32_t aoff = (uint32_t)(((lane & 7) + ((lane >> 4) & 1) * 8) * (LDA * 4)
                               + ((lane >> 3) & 1) * 16);

    float c[2][4][4];
#pragma unroll
    for (int mi = 0; mi < 2; mi++)
#pragma unroll
        for (int ni = 0; ni < 4; ni++)
#pragma unroll
            for (int j = 0; j < 4; j++) c[mi][ni][j] = 0.f;

    float4 av[4], bv[2];
#pragma unroll
    for (int i = 0; i < 4; i++) av[i] = *(const float4*)(aptr[i]);
#pragma unroll
    for (int p = 0; p < 2; p++)
        bv[p] = *(const float4*)(bbase + (size_t)(p * 4) * D_DIM);

    for (int it = 0; it < NS2; it++) {
        char* sA = dynsmem + (it & 1) * STAGE2;
        char* sB = sA + A_BYTES;
#pragma unroll
        for (int i = 0; i < 4; i++) {
            // g_inner already tf32-rounded: raw bit copy
            uint4 u = make_uint4(__float_as_uint(av[i].x), __float_as_uint(av[i].y),
                                 __float_as_uint(av[i].z), __float_as_uint(av[i].w));
            *(uint4*)(sA + (rA + i * 32) * (LDA * 4) + kv * 16) = u;
        }
        {
            float4 b2[4];
            b2[0] = bv[0]; b2[1] = bv[1];
            sts_B(sB, b2, 2, nhB, khB, lane);
        }
        __syncthreads();
        if (it + 1 < NS2) {
            int k0 = (it + 1) * 32;
#pragma unroll
            for (int i = 0; i < 4; i++) av[i] = *(const float4*)(aptr[i] + k0);
#pragma unroll
            for (int p = 0; p < 2; p++)
                bv[p] = *(const float4*)(bbase + (size_t)(k0 + p * 4) * D_DIM);
        }
        uint32_t aA = s2u(sA) + (uint32_t)(wm * 32 * (LDA * 4)) + aoff;
        uint32_t aB = s2u(sB) + (uint32_t)(wn * 32 * (LDA * 4)) + aoff;
#pragma unroll
        for (int kb = 0; kb < 4; kb++) {
            uint32_t koff = kb * 32;
            uint32_t a[2][4], f[2][4];
            ldsmA(a[0], aA + koff);
            ldsmA(a[1], aA + 16 * (LDA * 4) + koff);
            ldsm4(f[0], aB + koff);
            ldsm4(f[1], aB + 16 * (LDA * 4) + koff);
#pragma unroll
            for (int mi = 0; mi < 2; mi++)
#pragma unroll
                for (int j = 0; j < 2; j++) {
                    mma_tf32(c[mi][2 * j],     a[mi], &f[j][0]);
                    mma_tf32(c[mi][2 * j + 1], a[mi], &f[j][2]);
                }
        }
        __syncthreads();
    }

    // epilogue: gate-weighted atomic accumulate
#pragma unroll
    for (int mi = 0; mi < 2; mi++) {
#pragma unroll
        for (int ni = 0; ni < 4; ni++) {
            int col = n0 + wn * 32 + ni * 8 + t4 * 2;
            float b0 = bout[e * D_DIM + col], b1 = bout[e * D_DIM + col + 1];
#pragma unroll
            for (int h = 0; h < 2; h++) {
                int rowp = row0 + wm * 32 + mi * 16 + g4 + h * 8;
                int tok = g_pair_token[rowp];
                if (tok >= 0) {
                    float w = g_pair_w[rowp];
                    atomicAdd(&out[(size_t)tok * D_DIM + col],     w * (c[mi][ni][h * 2 + 0] + b0));
                    atomicAdd(&out[(size_t)tok * D_DIM + col + 1], w * (c[mi][ni][h * 2 + 1] + b1));
                }
            }
        }
    }
}

// ---------------------------------------------------------------------------
extern "C" void kernel_launch(void* const* d_in, const int* in_sizes, int n_in,
                              void* d_out, int out_size) {
    const float* states = (const float*)d_in[0];
    const float* Wg     = (const float*)d_in[1];
    const float* Win    = (const float*)d_in[2];
    const float* bin    = (const float*)d_in[3];
    const float* Wsc    = (const float*)d_in[4];
    const float* bsc    = (const float*)d_in[5];
    const float* Wout   = (const float*)d_in[6];
    const float* bout   = (const float*)d_in[7];
    float* out = (float*)d_out;

    static bool attr_set = false;
    if (!attr_set) {
        cudaFuncSetAttribute(gemm1_kernel, cudaFuncAttributeMaxDynamicSharedMemorySize, SMEM1);
        cudaFuncSetAttribute(gemm2_kernel, cudaFuncAttributeMaxDynamicSharedMemorySize, SMEM2);
        attr_set = true;
    }

    init_kernel<<<(out_size + 255) / 256, 256>>>(out, out_size);
    router_kernel<<<N_TOK / 8, 256>>>(states, Wg);
    setup_kernel<<<1, 32>>>();
    scatter_kernel<<<(NPAIR + 255) / 256, 256>>>();
    gemm1_kernel<<<dim3(F_DIM / 64, MAXTILES), 256, SMEM1>>>(states, Win, bin, Wsc, bsc);
    gemm2_kernel<<<dim3(D_DIM / 64, MAXTILES), 256, SMEM2>>>(Wout, bout, out);
}

// round 11
// speedup vs baseline: 1.0001x; 1.0001x over previous
#include <cuda_runtime.h>
#include <cuda_bf16.h>
#include <math.h>
#include <stdint.h>

// Problem constants (fixed by the dataset)
#define D_DIM   1024
#define F_DIM   2048
#define E_NUM   8
#define N_TOK   2048
#define NPAIR   4096
#define PADROWS 5120
#define MAXTILES 40
#define NS1 32            // 1024/32 K-stages, GEMM1
#define NS2 64            // 2048/32 K-stages, GEMM2
#define LDA 36            // fp32 elems per row (32 + 4 pad) -> 144B stride

#define A_BYTES  (128 * LDA * 4)          // 18432
#define B_BYTES  (64 * LDA * 4)           // 9216
#define STAGE1   (A_BYTES + 2 * B_BYTES)  // 36864
#define STAGE2   (A_BYTES + B_BYTES)      // 27648
#define SMEM1    (2 * STAGE1)             // 73728
#define SMEM2    (2 * STAGE2)             // 55296

// Scratch (device globals — no runtime allocation allowed)
__device__ float g_inner[(size_t)PADROWS * F_DIM];   // tf32-rounded fp32
__device__ int   g_pair_token[PADROWS];
__device__ float g_pair_w[PADROWS];
__device__ int   g_topi[N_TOK * 2];
__device__ float g_topw[N_TOK * 2];
__device__ int   g_counts[E_NUM];
__device__ int   g_cursor[E_NUM];
__device__ int   g_tile_e[MAXTILES];

__device__ __forceinline__ uint32_t f2tf(float f) {
    uint32_t u;
    asm("cvt.rna.tf32.f32 %0, %1;" : "=r"(u) : "f"(f));
    return u;
}
__device__ __forceinline__ uint32_t s2u(const void* p) {
    return (uint32_t)__cvta_generic_to_shared((void*)p);
}
__device__ __forceinline__ void mma_tf32(float c[4], const uint32_t a[4],
                                         const uint32_t b[2]) {
    asm volatile(
        "mma.sync.aligned.m16n8k8.row.col.f32.tf32.tf32.f32 "
        "{%0,%1,%2,%3}, {%4,%5,%6,%7}, {%8,%9}, {%0,%1,%2,%3};\n"
        : "+f"(c[0]), "+f"(c[1]), "+f"(c[2]), "+f"(c[3])
        : "r"(a[0]), "r"(a[1]), "r"(a[2]), "r"(a[3]), "r"(b[0]), "r"(b[1]));
}
__device__ __forceinline__ void ldsm4(uint32_t r[4], uint32_t addr) {
    asm volatile("ldmatrix.sync.aligned.m8n8.x4.shared.b16 {%0,%1,%2,%3}, [%4];"
                 : "=r"(r[0]), "=r"(r[1]), "=r"(r[2]), "=r"(r[3]) : "r"(addr));
}
// ldsm4 with our aoff returns {(r0-7,k0-3),(r0-7,k4-7),(r8-15,k0-3),(r8-15,k4-7)}.
// The tf32 A fragment wants {a0,a1,a2,a3}={(g4,t4),(g4+8,t4),(g4,t4+4),(g4+8,t4+4)}
// = {r0, r2, r1, r3}  -> reorder here.
__device__ __forceinline__ void ldsmA(uint32_t a[4], uint32_t addr) {
    uint32_t r[4];
    ldsm4(r, addr);
    a[0] = r[0]; a[1] = r[2]; a[2] = r[1]; a[3] = r[3];
}

// ---------------------------------------------------------------------------
// small kernels
// ---------------------------------------------------------------------------
__global__ void init_kernel(float* out, int out_size) {
    int idx = blockIdx.x * blockDim.x + threadIdx.x;
    if (idx < out_size) out[idx] = 0.f;
    if (idx < PADROWS)  g_pair_token[idx] = -1;
    if (idx < E_NUM)    g_counts[idx] = 0;
}

__global__ void router_kernel(const float* __restrict__ x,
                              const float* __restrict__ Wg) {
    int warp = threadIdx.x >> 5;
    int lane = threadIdx.x & 31;
    int n = blockIdx.x * 8 + warp;
    if (n >= N_TOK) return;
    float acc[E_NUM];
#pragma unroll
    for (int e = 0; e < E_NUM; e++) acc[e] = 0.f;
    const float* xr = x + (size_t)n * D_DIM;
    for (int d = lane; d < D_DIM; d += 32) {
        float xv = xr[d];
#pragma unroll
        for (int e = 0; e < E_NUM; e++) acc[e] += xv * Wg[d * E_NUM + e];
    }
#pragma unroll
    for (int e = 0; e < E_NUM; e++) {
#pragma unroll
        for (int off = 16; off > 0; off >>= 1)
            acc[e] += __shfl_xor_sync(0xffffffffu, acc[e], off);
    }
    if (lane == 0) {
        float m = acc[0];
#pragma unroll
        for (int e = 1; e < E_NUM; e++) m = fmaxf(m, acc[e]);
        float p[E_NUM];
#pragma unroll
        for (int e = 0; e < E_NUM; e++) p[e] = expf(acc[e] - m);
        int i1 = 0;
#pragma unroll
        for (int e = 1; e < E_NUM; e++) if (p[e] > p[i1]) i1 = e;
        int i2 = (i1 == 0) ? 1 : 0;
#pragma unroll
        for (int e = 0; e < E_NUM; e++)
            if (e != i1 && p[e] > p[i2]) i2 = e;
        float inv = 1.f / (p[i1] + p[i2]);
        g_topi[n * 2 + 0] = i1;  g_topw[n * 2 + 0] = p[i1] * inv;
        g_topi[n * 2 + 1] = i2;  g_topw[n * 2 + 1] = p[i2] * inv;
        atomicAdd(&g_counts[i1], 1);
        atomicAdd(&g_counts[i2], 1);
    }
}

__global__ void setup_kernel() {
    if (threadIdx.x != 0 || blockIdx.x != 0) return;
    int off = 0;
    int pad[E_NUM];
    for (int e = 0; e < E_NUM; e++) {
        g_cursor[e] = off;
        int p = ((g_counts[e] + 127) / 128) * 128;
        pad[e] = p;
        off += p;
    }
    int t = 0;
    for (int e = 0; e < E_NUM; e++)
        for (int r = 0; r < pad[e]; r += 128) g_tile_e[t++] = e;
    for (; t < MAXTILES; t++) g_tile_e[t] = -1;
}

__global__ void scatter_kernel() {
    int idx = blockIdx.x * blockDim.x + threadIdx.x;
    if (idx >= NPAIR) return;
    int e = g_topi[idx];
    int pos = atomicAdd(&g_cursor[e], 1);
    g_pair_token[pos] = idx >> 1;
    g_pair_w[pos] = g_topw[idx];
}

// ---------------------------------------------------------------------------
// B-tile store: cvt.rna + 4x4 shfl transpose + STS.128 (conflict-free).
// Lane (a = lane>>2, b = lane&3) loaded bv[p] = W[khb+4p+b][n cols nh+a*4..+3].
// After transpose lane holds n = nh + a*4 + b, k-run of 4 at khb+4p.
// ---------------------------------------------------------------------------
__device__ __forceinline__ void sts_B(char* sB, const float4* bv, int np,
                                      int nh, int khb, int lane) {
    int a = lane >> 2, b = lane & 3;
#pragma unroll
    for (int p = 0; p < 4; p++) {
        if (p >= np) break;
        uint32_t t[4] = { f2tf(bv[p].x), f2tf(bv[p].y), f2tf(bv[p].z), f2tf(bv[p].w) };
        uint32_t w4[4];
#pragma unroll
        for (int s = 0; s < 4; s++) {
            int j = (b - s) & 3;
            w4[j] = __shfl_sync(0xffffffffu, t[(b + s) & 3], (lane & ~3) | j);
        }
        int n = nh + a * 4 + b;
        *(uint4*)(sB + n * (LDA * 4) + (khb + p * 4) * 4) =
            make_uint4(w4[0], w4[1], w4[2], w4[3]);
    }
}

// ---------------------------------------------------------------------------
// GEMM1: inner = gelu(X@W_in + b_in) * (X@W_scale + b_scale)
// Grid (F/64, MAXTILES). 256 thr, warps: wm=warp&3 (32 rows), wn=warp>>2 (32 cols).
// ---------------------------------------------------------------------------
extern __shared__ __align__(16) char dynsmem[];

__global__ __launch_bounds__(256, 1)
void gemm1_kernel(const float* __restrict__ x,   const float* __restrict__ Win,
                  const float* __restrict__ bin, const float* __restrict__ Wsc,
                  const float* __restrict__ bsc) {
    int e = g_tile_e[blockIdx.y];
    if (e < 0) return;
    int row0 = blockIdx.y * 128;
    int n0   = blockIdx.x * 64;

    int tid = threadIdx.x;
    int lane = tid & 31, warp = tid >> 5;
    int wm = warp & 3, wn = warp >> 2;
    int g4 = lane >> 2, t4 = lane & 3;

    // A gather mapping: rows rA + 32i, fixed kv
    int rA = tid >> 3, kv = tid & 7;
    const float* xptr[4];
    bool tval[4];
#pragma unroll
    for (int i = 0; i < 4; i++) {
        int tok = g_pair_token[row0 + rA + i * 32];
        tval[i] = (tok >= 0);
        xptr[i] = x + (size_t)(tok >= 0 ? tok : 0) * D_DIM + kv * 4;
    }
    // B loader mapping: warp -> matrix (warp&1), k-half khB, n-half nhB
    int aq = lane >> 2, bq = lane & 3;
    int khB = ((warp >> 1) & 1) * 16;
    int nhB = (warp >> 2) * 32;
    const float* wsel = (warp & 1) ? Wsc : Win;
    const float* bbase = wsel + ((size_t)e * D_DIM + khB + bq) * F_DIM + n0 + nhB + aq * 4;

    // ldmatrix per-lane offset: lanes 0-7 rows 0-7 k0-3; 8-15 rows 0-7 k4-7;
    // 16-23 rows 8-15 k0-3; 24-31 rows 8-15 k4-7.
    uint32_t aoff = (uint32_t)(((lane & 7) + ((lane >> 4) & 1) * 8) * (LDA * 4)
                               + ((lane >> 3) & 1) * 16);

    float cH[2][4][4], cS[2][4][4];
#pragma unroll
    for (int mi = 0; mi < 2; mi++)
#pragma unroll
        for (int ni = 0; ni < 4; ni++)
#pragma unroll
            for (int j = 0; j < 4; j++) { cH[mi][ni][j] = 0.f; cS[mi][ni][j] = 0.f; }

    float4 av[4], bv[4];
    // prologue loads for k0 = 0
#pragma unroll
    for (int i = 0; i < 4; i++)
        av[i] = tval[i] ? *(const float4*)(xptr[i]) : make_float4(0.f, 0.f, 0.f, 0.f);
#pragma unroll
    for (int p = 0; p < 4; p++)
        bv[p] = *(const float4*)(bbase + (size_t)(p * 4) * F_DIM);

    for (int it = 0; it < NS1; it++) {
        char* sA  = dynsmem + (it & 1) * STAGE1;
        char* sB1 = sA + A_BYTES;
        char* sB2 = sB1 + B_BYTES;
        // store current stage
#pragma unroll
        for (int i = 0; i < 4; i++) {
            uint4 u = make_uint4(f2tf(av[i].x), f2tf(av[i].y), f2tf(av[i].z), f2tf(av[i].w));
            *(uint4*)(sA + (rA + i * 32) * (LDA * 4) + kv * 16) = u;
        }
        sts_B((warp & 1) ? sB2 : sB1, bv, 4, nhB, khB, lane);
        __syncthreads();
        // prefetch next stage
        if (it + 1 < NS1) {
            int k0 = (it + 1) * 32;
#pragma unroll
            for (int i = 0; i < 4; i++)
                av[i] = tval[i] ? *(const float4*)(xptr[i] + k0)
                                : make_float4(0.f, 0.f, 0.f, 0.f);
#pragma unroll
            for (int p = 0; p < 4; p++)
                bv[p] = *(const float4*)(bbase + (size_t)(k0 + p * 4) * F_DIM);
        }
        // compute
        uint32_t aA  = s2u(sA)  + (uint32_t)(wm * 32 * (LDA * 4)) + aoff;
        uint32_t aB1 = s2u(sB1) + (uint32_t)(wn * 32 * (LDA * 4)) + aoff;
        uint32_t aB2 = s2u(sB2) + (uint32_t)(wn * 32 * (LDA * 4)) + aoff;
#pragma unroll
        for (int kb = 0; kb < 4; kb++) {
            uint32_t koff = kb * 32;
            uint32_t a[2][4], f1[2][4], f2[2][4];
            ldsmA(a[0], aA + koff);
            ldsmA(a[1], aA + 16 * (LDA * 4) + koff);
            ldsm4(f1[0], aB1 + koff);
            ldsm4(f1[1], aB1 + 16 * (LDA * 4) + koff);
            ldsm4(f2[0], aB2 + koff);
            ldsm4(f2[1], aB2 + 16 * (LDA * 4) + koff);
#pragma unroll
            for (int mi = 0; mi < 2; mi++)
#pragma unroll
                for (int j = 0; j < 2; j++) {
                    mma_tf32(cH[mi][2 * j],     a[mi], &f1[j][0]);
                    mma_tf32(cH[mi][2 * j + 1], a[mi], &f1[j][2]);
                    mma_tf32(cS[mi][2 * j],     a[mi], &f2[j][0]);
                    mma_tf32(cS[mi][2 * j + 1], a[mi], &f2[j][2]);
                }
        }
        __syncthreads();
    }

    // epilogue: exact GELU gate, tf32-rounded fp32 store
#pragma unroll
    for (int mi = 0; mi < 2; mi++) {
#pragma unroll
        for (int ni = 0; ni < 4; ni++) {
            int col = n0 + wn * 32 + ni * 8 + t4 * 2;
            float bi0 = bin[e * F_DIM + col], bi1 = bin[e * F_DIM + col + 1];
            float bs0 = bsc[e * F_DIM + col], bs1 = bsc[e * F_DIM + col + 1];
#pragma unroll
            for (int h = 0; h < 2; h++) {
                int row = row0 + wm * 32 + mi * 16 + g4 + h * 8;
                float h0 = cH[mi][ni][h * 2 + 0] + bi0;
                float h1 = cH[mi][ni][h * 2 + 1] + bi1;
                float s0 = cS[mi][ni][h * 2 + 0] + bs0;
                float s1 = cS[mi][ni][h * 2 + 1] + bs1;
                float gl0 = 0.5f * h0 * (1.f + erff(h0 * 0.70710678118654752f));
                float gl1 = 0.5f * h1 * (1.f + erff(h1 * 0.70710678118654752f));
                float2 o;
                o.x = __uint_as_float(f2tf(gl0 * s0));
                o.y = __uint_as_float(f2tf(gl1 * s1));
                *(float2*)(g_inner + (size_t)row * F_DIM + col) = o;
            }
        }
    }
}

// ---------------------------------------------------------------------------
// GEMM2: y = inner @ W_out + b_out; out[token] += gate * y (atomic)
// Grid (D/64, MAXTILES)
// ---------------------------------------------------------------------------
__global__ __launch_bounds__(256, 1)
void gemm2_kernel(const float* __restrict__ Wout, const float* __restrict__ bout,
                  float* __restrict__ out) {
    int e = g_tile_e[blockIdx.y];
    if (e < 0) return;
    int row0 = blockIdx.y * 128;
    int n0   = blockIdx.x * 64;

    int tid = threadIdx.x;
    int lane = tid & 31, warp = tid >> 5;
    int wm = warp & 3, wn = warp >> 2;
    int g4 = lane >> 2, t4 = lane & 3;

    int rA = tid >> 3, kv = tid & 7;
    const float* aptr[4];
#pragma unroll
    for (int i = 0; i < 4; i++)
        aptr[i] = g_inner + (size_t)(row0 + rA + i * 32) * F_DIM + kv * 4;

    int aq = lane >> 2, bq = lane & 3;
    int khB = (warp & 3) * 8;
    int nhB = (warp >> 2) * 32;
    const float* bbase = Wout + ((size_t)e * F_DIM + khB + bq) * D_DIM + n0 + nhB + aq * 4;

    uint32_t aoff = (uint32_t)(((lane & 7) + ((lane >> 4) & 1) * 8) * (LDA * 4)
                               + ((lane >> 3) & 1) * 16);

    float c[2][4][4];
#pragma unroll
    for (int mi = 0; mi < 2; mi++)
#pragma unroll
        for (int ni = 0; ni < 4; ni++)
#pragma unroll
            for (int j = 0; j < 4; j++) c[mi][ni][j] = 0.f;

    float4 av[4], bv[2];
#pragma unroll
    for (int i = 0; i < 4; i++) av[i] = *(const float4*)(aptr[i]);
#pragma unroll
    for (int p = 0; p < 2; p++)
        bv[p] = *(const float4*)(bbase + (size_t)(p * 4) * D_DIM);

    for (int it = 0; it < NS2; it++) {
        char* sA = dynsmem + (it & 1) * STAGE2;
        char* sB = sA + A_BYTES;
#pragma unroll
        for (int i = 0; i < 4; i++) {
            // g_inner already tf32-rounded: raw bit copy
            uint4 u = make_uint4(__float_as_uint(av[i].x), __float_as_uint(av[i].y),
                                 __float_as_uint(av[i].z), __float_as_uint(av[i].w));
            *(uint4*)(sA + (rA + i * 32) * (LDA * 4) + kv * 16) = u;
        }
        {
            float4 b2[4];
            b2[0] = bv[0]; b2[1] = bv[1];
            sts_B(sB, b2, 2, nhB, khB, lane);
        }
        __syncthreads();
        if (it + 1 < NS2) {
            int k0 = (it + 1) * 32;
#pragma unroll
            for (int i = 0; i < 4; i++) av[i] = *(const float4*)(aptr[i] + k0);
#pragma unroll
            for (int p = 0; p < 2; p++)
                bv[p] = *(const float4*)(bbase + (size_t)(k0 + p * 4) * D_DIM);
        }
        uint32_t aA = s2u(sA) + (uint32_t)(wm * 32 * (LDA * 4)) + aoff;
        uint32_t aB = s2u(sB) + (uint32_t)(wn * 32 * (LDA * 4)) + aoff;
#pragma unroll
        for (int kb = 0; kb < 4; kb++) {
            uint32_t koff = kb * 32;
            uint32_t a[2][4], f[2][4];
            ldsmA(a[0], aA + koff);
            ldsmA(a[1], aA + 16 * (LDA * 4) + koff);
            ldsm4(f[0], aB + koff);
            ldsm4(f[1], aB + 16 * (LDA * 4) + koff);
#pragma unroll
            for (int mi = 0; mi < 2; mi++)
#pragma unroll
                for (int j = 0; j < 2; j++) {
                    mma_tf32(c[mi][2 * j],     a[mi], &f[j][0]);
                    mma_tf32(c[mi][2 * j + 1], a[mi], &f[j][2]);
                }
        }
        __syncthreads();
    }

    // epilogue: gate-weighted atomic accumulate
#pragma unroll
    for (int mi = 0; mi < 2; mi++) {
#pragma unroll
        for (int ni = 0; ni < 4; ni++) {
            int col = n0 + wn * 32 + ni * 8 + t4 * 2;
            float b0 = bout[e * D_DIM + col], b1 = bout[e * D_DIM + col + 1];
#pragma unroll
            for (int h = 0; h < 2; h++) {
                int rowp = row0 + wm * 32 + mi * 16 + g4 + h * 8;
                int tok = g_pair_token[rowp];
                if (tok >= 0) {
                    float w = g_pair_w[rowp];
                    atomicAdd(&out[(size_t)tok * D_DIM + col],     w * (c[mi][ni][h * 2 + 0] + b0));
                    atomicAdd(&out[(size_t)tok * D_DIM + col + 1], w * (c[mi][ni][h * 2 + 1] + b1));
                }
            }
        }
    }
}

// ---------------------------------------------------------------------------
extern "C" void kernel_launch(void* const* d_in, const int* in_sizes, int n_in,
                              void* d_out, int out_size) {
    const float* states = (const float*)d_in[0];
    const float* Wg     = (const float*)d_in[1];
    const float* Win    = (const float*)d_in[2];
    const float* bin    = (const float*)d_in[3];
    const float* Wsc    = (const float*)d_in[4];
    const float* bsc    = (const float*)d_in[5];
    const float* Wout   = (const float*)d_in[6];
    const float* bout   = (const float*)d_in[7];
    float* out = (float*)d_out;

    static bool attr_set = false;
    if (!attr_set) {
        cudaFuncSetAttribute(gemm1_kernel, cudaFuncAttributeMaxDynamicSharedMemorySize, SMEM1);
        cudaFuncSetAttribute(gemm2_kernel, cudaFuncAttributeMaxDynamicSharedMemorySize, SMEM2);
        attr_set = true;
    }

    init_kernel<<<(out_size + 255) / 256, 256>>>(out, out_size);
    router_kernel<<<N_TOK / 8, 256>>>(states, Wg);
    setup_kernel<<<1, 32>>>();
    scatter_kernel<<<(NPAIR + 255) / 256, 256>>>();
    gemm1_kernel<<<dim3(F_DIM / 64, MAXTILES), 256, SMEM1>>>(states, Win, bin, Wsc, bsc);
    gemm2_kernel<<<dim3(D_DIM / 64, MAXTILES), 256, SMEM2>>>(Wout, bout, out);
}

// round 13
// speedup vs baseline: 1.3220x; 1.3219x over previous
#include <cuda_runtime.h>
#include <cuda_bf16.h>
#include <math.h>
#include <stdint.h>

// Problem constants (fixed by the dataset)
#define D_DIM   1024
#define F_DIM   2048
#define E_NUM   8
#define N_TOK   2048
#define NPAIR   4096
#define PADROWS 5120
#define MAXTILES 40
#define NS1 32            // 1024/32 K-stages, GEMM1
#define NS2 64            // 2048/32 K-stages, GEMM2
#define LDA 36            // fp32 elems per smem row (32 + 4 pad) -> 144B stride

#define A_BYTES  (128 * LDA * 4)          // 18432
#define B_BYTES  (64 * LDA * 4)           // 9216
#define STAGE1   (A_BYTES + 2 * B_BYTES)  // 36864
#define STAGE2   (A_BYTES + B_BYTES)      // 27648
#define NSTAGE   3
#define SMEM1    (NSTAGE * STAGE1)        // 110592
#define SMEM2    (NSTAGE * STAGE2)        // 82944

// Scratch (device globals — no runtime allocation allowed)
__device__ float g_inner[(size_t)PADROWS * F_DIM];         // tf32-rounded fp32
__device__ float g_x_tf[(size_t)N_TOK * D_DIM];            // tf32-rounded states
__device__ float g_win_t[(size_t)E_NUM * F_DIM * D_DIM];   // [e][n][k] tf32
__device__ float g_wsc_t[(size_t)E_NUM * F_DIM * D_DIM];   // [e][n][k] tf32
__device__ float g_wout_t[(size_t)E_NUM * D_DIM * F_DIM];  // [e][n][k] tf32
__device__ int   g_pair_token[PADROWS];
__device__ float g_pair_w[PADROWS];
__device__ int   g_topi[N_TOK * 2];
__device__ float g_topw[N_TOK * 2];
__device__ int   g_counts[E_NUM];
__device__ int   g_cursor[E_NUM];
__device__ int   g_tile_e[MAXTILES];

__device__ __forceinline__ uint32_t f2tf(float f) {
    uint32_t u;
    asm("cvt.rna.tf32.f32 %0, %1;" : "=r"(u) : "f"(f));
    return u;
}
__device__ __forceinline__ uint32_t s2u(const void* p) {
    return (uint32_t)__cvta_generic_to_shared((void*)p);
}
__device__ __forceinline__ void cpa16(uint32_t dst, const void* src, uint32_t sz) {
    asm volatile("cp.async.cg.shared.global [%0], [%1], 16, %2;"
                 :: "r"(dst), "l"(src), "r"(sz) : "memory");
}
#define CP_COMMIT() asm volatile("cp.async.commit_group;" ::: "memory")
#define CP_WAIT0()  asm volatile("cp.async.wait_group 0;" ::: "memory")
#define CP_WAIT1()  asm volatile("cp.async.wait_group 1;" ::: "memory")
#define CP_WAIT2()  asm volatile("cp.async.wait_group 2;" ::: "memory")

__device__ __forceinline__ void mma_tf32(float c[4], const uint32_t a[4],
                                         const uint32_t b[2]) {
    asm volatile(
        "mma.sync.aligned.m16n8k8.row.col.f32.tf32.tf32.f32 "
        "{%0,%1,%2,%3}, {%4,%5,%6,%7}, {%8,%9}, {%0,%1,%2,%3};\n"
        : "+f"(c[0]), "+f"(c[1]), "+f"(c[2]), "+f"(c[3])
        : "r"(a[0]), "r"(a[1]), "r"(a[2]), "r"(a[3]), "r"(b[0]), "r"(b[1]));
}
__device__ __forceinline__ void ldsm4(uint32_t r[4], uint32_t addr) {
    asm volatile("ldmatrix.sync.aligned.m8n8.x4.shared.b16 {%0,%1,%2,%3}, [%4];"
                 : "=r"(r[0]), "=r"(r[1]), "=r"(r[2]), "=r"(r[3]) : "r"(addr));
}
// A fragment wants {r0, r2, r1, r3} of the x4 result (verified round 11).
__device__ __forceinline__ void ldsmA(uint32_t a[4], uint32_t addr) {
    uint32_t r[4];
    ldsm4(r, addr);
    a[0] = r[0]; a[1] = r[2]; a[2] = r[1]; a[3] = r[3];
}

// ---------------------------------------------------------------------------
// small kernels
// ---------------------------------------------------------------------------
__global__ void init_kernel(float* out, int out_size) {
    int idx = blockIdx.x * blockDim.x + threadIdx.x;
    if (idx < out_size) out[idx] = 0.f;
    if (idx < PADROWS)  g_pair_token[idx] = -1;
    if (idx < E_NUM)    g_counts[idx] = 0;
}

__global__ void router_kernel(const float* __restrict__ x,
                              const float* __restrict__ Wg) {
    int warp = threadIdx.x >> 5;
    int lane = threadIdx.x & 31;
    int n = blockIdx.x * 8 + warp;
    if (n >= N_TOK) return;
    float acc[E_NUM];
#pragma unroll
    for (int e = 0; e < E_NUM; e++) acc[e] = 0.f;
    const float* xr = x + (size_t)n * D_DIM;
    for (int d = lane; d < D_DIM; d += 32) {
        float xv = xr[d];
#pragma unroll
        for (int e = 0; e < E_NUM; e++) acc[e] += xv * Wg[d * E_NUM + e];
    }
#pragma unroll
    for (int e = 0; e < E_NUM; e++) {
#pragma unroll
        for (int off = 16; off > 0; off >>= 1)
            acc[e] += __shfl_xor_sync(0xffffffffu, acc[e], off);
    }
    if (lane == 0) {
        float m = acc[0];
#pragma unroll
        for (int e = 1; e < E_NUM; e++) m = fmaxf(m, acc[e]);
        float p[E_NUM];
#pragma unroll
        for (int e = 0; e < E_NUM; e++) p[e] = expf(acc[e] - m);
        int i1 = 0;
#pragma unroll
        for (int e = 1; e < E_NUM; e++) if (p[e] > p[i1]) i1 = e;
        int i2 = (i1 == 0) ? 1 : 0;
#pragma unroll
        for (int e = 0; e < E_NUM; e++)
            if (e != i1 && p[e] > p[i2]) i2 = e;
        float inv = 1.f / (p[i1] + p[i2]);
        g_topi[n * 2 + 0] = i1;  g_topw[n * 2 + 0] = p[i1] * inv;
        g_topi[n * 2 + 1] = i2;  g_topw[n * 2 + 1] = p[i2] * inv;
        atomicAdd(&g_counts[i1], 1);
        atomicAdd(&g_counts[i2], 1);
    }
}

__global__ void setup_kernel() {
    if (threadIdx.x != 0 || blockIdx.x != 0) return;
    int off = 0;
    int pad[E_NUM];
    for (int e = 0; e < E_NUM; e++) {
        g_cursor[e] = off;
        int p = ((g_counts[e] + 127) / 128) * 128;
        pad[e] = p;
        off += p;
    }
    int t = 0;
    for (int e = 0; e < E_NUM; e++)
        for (int r = 0; r < pad[e]; r += 128) g_tile_e[t++] = e;
    for (; t < MAXTILES; t++) g_tile_e[t] = -1;
}

__global__ void scatter_kernel() {
    int idx = blockIdx.x * blockDim.x + threadIdx.x;
    if (idx >= NPAIR) return;
    int e = g_topi[idx];
    int pos = atomicAdd(&g_cursor[e], 1);
    g_pair_token[pos] = idx >> 1;
    g_pair_w[pos] = g_topw[idx];
}

// ---------------------------------------------------------------------------
// convert kernels. NOTE: destinations are __device__ globals and MUST be
// resolved in device code (host-side symbol decay gives the host shadow
// address — the round-12 bug).
// ---------------------------------------------------------------------------
__global__ void convert_x_kernel(const float* __restrict__ x) {
    int idx = blockIdx.x * blockDim.x + threadIdx.x;
    float4 v = *(const float4*)(x + (size_t)idx * 4);
    uint4 u = make_uint4(f2tf(v.x), f2tf(v.y), f2tf(v.z), f2tf(v.w));
    *(uint4*)(g_x_tf + (size_t)idx * 4) = u;
}

// src [e][Kd][Nd] -> dst[which] [e][Nd][Kd], tf32-rounded. Grid (Nd/32, Kd/32, E)
__global__ void transpose_w_kernel(const float* __restrict__ src, int which,
                                   int Kd, int Nd) {
    __shared__ float t[32][33];
    float* dstg = (which == 0) ? g_win_t : (which == 1) ? g_wsc_t : g_wout_t;
    const float* s = src + (size_t)blockIdx.z * Kd * Nd;
    float* d = dstg + (size_t)blockIdx.z * Kd * Nd;
    int n0 = blockIdx.x * 32, k0 = blockIdx.y * 32;
    int tx = threadIdx.x & 31, ty = threadIdx.x >> 5;
#pragma unroll
    for (int i = 0; i < 4; i++)
        t[ty + i * 8][tx] = s[(size_t)(k0 + ty + i * 8) * Nd + n0 + tx];
    __syncthreads();
#pragma unroll
    for (int i = 0; i < 4; i++)
        d[(size_t)(n0 + ty + i * 8) * Kd + k0 + tx] =
            __uint_as_float(f2tf(t[tx][ty + i * 8]));
}

// ---------------------------------------------------------------------------
// GEMM1: inner = gelu(X@W_in + b_in) * (X@W_scale + b_scale)
// Grid (F/64, MAXTILES). cp.async 3-stage pipeline, ldmatrix fragments.
// ---------------------------------------------------------------------------
extern __shared__ __align__(16) char dynsmem[];

__global__ __launch_bounds__(256, 2)
void gemm1_kernel(const float* __restrict__ bin, const float* __restrict__ bsc) {
    int e = g_tile_e[blockIdx.y];
    if (e < 0) return;
    int row0 = blockIdx.y * 128;
    int n0   = blockIdx.x * 64;

    int tid = threadIdx.x;
    int lane = tid & 31, warp = tid >> 5;
    int wm = warp & 3, wn = warp >> 2;
    int g4 = lane >> 2, t4 = lane & 3;

    // A loader: row = tid>>1, 4 16B chunks starting at (tid&1)*4
    int rowA = tid >> 1, ac = (tid & 1) * 4;
    int tok = g_pair_token[row0 + rowA];
    uint32_t asz = (tok >= 0) ? 16u : 0u;
    const float* asrc = g_x_tf + (size_t)(tok >= 0 ? tok : 0) * D_DIM + ac * 4;
    // B loader: n-row = tid>>2, chunk pair kc0 = (tid&3)*2
    int bn = tid >> 2, kc0 = (tid & 3) * 2;
    const float* b1src = g_win_t + ((size_t)e * F_DIM + n0 + bn) * D_DIM + kc0 * 4;
    const float* b2src = g_wsc_t + ((size_t)e * F_DIM + n0 + bn) * D_DIM + kc0 * 4;

    uint32_t aoff = (uint32_t)(((lane & 7) + ((lane >> 4) & 1) * 8) * (LDA * 4)
                               + ((lane >> 3) & 1) * 16);

    float cH[2][4][4], cS[2][4][4];
#pragma unroll
    for (int mi = 0; mi < 2; mi++)
#pragma unroll
        for (int ni = 0; ni < 4; ni++)
#pragma unroll
            for (int j = 0; j < 4; j++) { cH[mi][ni][j] = 0.f; cS[mi][ni][j] = 0.f; }

    auto issue = [&](int it) {
        char* sA  = dynsmem + (it % NSTAGE) * STAGE1;
        char* sB1 = sA + A_BYTES;
        char* sB2 = sB1 + B_BYTES;
        int k0 = it * 32;
        uint32_t da = s2u(sA) + rowA * (LDA * 4) + ac * 16;
#pragma unroll
        for (int i = 0; i < 4; i++)
            cpa16(da + i * 16, asrc + k0 + i * 4, asz);
        uint32_t db1 = s2u(sB1) + bn * (LDA * 4) + kc0 * 16;
        uint32_t db2 = s2u(sB2) + bn * (LDA * 4) + kc0 * 16;
#pragma unroll
        for (int i = 0; i < 2; i++) {
            cpa16(db1 + i * 16, b1src + k0 + i * 4, 16);
            cpa16(db2 + i * 16, b2src + k0 + i * 4, 16);
        }
        CP_COMMIT();
    };

    issue(0);
    issue(1);

    for (int it = 0; it < NS1; it++) {
        // issue newest first, then wait leaving in-flight stages pending.
        if (it + 2 < NS1) { issue(it + 2); CP_WAIT2(); }
        else if (it + 1 < NS1) { CP_WAIT1(); }
        else { CP_WAIT0(); }
        __syncthreads();

        char* sA  = dynsmem + (it % NSTAGE) * STAGE1;
        char* sB1 = sA + A_BYTES;
        char* sB2 = sB1 + B_BYTES;
        uint32_t aA  = s2u(sA)  + (uint32_t)(wm * 32 * (LDA * 4)) + aoff;
        uint32_t aB1 = s2u(sB1) + (uint32_t)(wn * 32 * (LDA * 4)) + aoff;
        uint32_t aB2 = s2u(sB2) + (uint32_t)(wn * 32 * (LDA * 4)) + aoff;
#pragma unroll
        for (int kb = 0; kb < 4; kb++) {
            uint32_t koff = kb * 32;
            uint32_t a[2][4], f1[2][4], f2[2][4];
            ldsmA(a[0], aA + koff);
            ldsmA(a[1], aA + 16 * (LDA * 4) + koff);
            ldsm4(f1[0], aB1 + koff);
            ldsm4(f1[1], aB1 + 16 * (LDA * 4) + koff);
            ldsm4(f2[0], aB2 + koff);
            ldsm4(f2[1], aB2 + 16 * (LDA * 4) + koff);
#pragma unroll
            for (int mi = 0; mi < 2; mi++)
#pragma unroll
                for (int j = 0; j < 2; j++) {
                    mma_tf32(cH[mi][2 * j],     a[mi], &f1[j][0]);
                    mma_tf32(cH[mi][2 * j + 1], a[mi], &f1[j][2]);
                    mma_tf32(cS[mi][2 * j],     a[mi], &f2[j][0]);
                    mma_tf32(cS[mi][2 * j + 1], a[mi], &f2[j][2]);
                }
        }
        __syncthreads();
    }

    // epilogue: exact GELU gate, tf32-rounded fp32 store
#pragma unroll
    for (int mi = 0; mi < 2; mi++) {
#pragma unroll
        for (int ni = 0; ni < 4; ni++) {
            int col = n0 + wn * 32 + ni * 8 + t4 * 2;
            float bi0 = bin[e * F_DIM + col], bi1 = bin[e * F_DIM + col + 1];
            float bs0 = bsc[e * F_DIM + col], bs1 = bsc[e * F_DIM + col + 1];
#pragma unroll
            for (int h = 0; h < 2; h++) {
                int row = row0 + wm * 32 + mi * 16 + g4 + h * 8;
                float h0 = cH[mi][ni][h * 2 + 0] + bi0;
                float h1 = cH[mi][ni][h * 2 + 1] + bi1;
                float s0 = cS[mi][ni][h * 2 + 0] + bs0;
                float s1 = cS[mi][ni][h * 2 + 1] + bs1;
                float gl0 = 0.5f * h0 * (1.f + erff(h0 * 0.70710678118654752f));
                float gl1 = 0.5f * h1 * (1.f + erff(h1 * 0.70710678118654752f));
                float2 o;
                o.x = __uint_as_float(f2tf(gl0 * s0));
                o.y = __uint_as_float(f2tf(gl1 * s1));
                *(float2*)(g_inner + (size_t)row * F_DIM + col) = o;
            }
        }
    }
}

// ---------------------------------------------------------------------------
// GEMM2: y = inner @ W_out + b_out; out[token] += gate * y (atomic)
// Grid (D/64, MAXTILES)
// ---------------------------------------------------------------------------
__global__ __launch_bounds__(256, 2)
void gemm2_kernel(const float* __restrict__ bout, float* __restrict__ out) {
    int e = g_tile_e[blockIdx.y];
    if (e < 0) return;
    int row0 = blockIdx.y * 128;
    int n0   = blockIdx.x * 64;

    int tid = threadIdx.x;
    int lane = tid & 31, warp = tid >> 5;
    int wm = warp & 3, wn = warp >> 2;
    int g4 = lane >> 2, t4 = lane & 3;

    int rowA = tid >> 1, ac = (tid & 1) * 4;
    const float* asrc = g_inner + (size_t)(row0 + rowA) * F_DIM + ac * 4;
    int bn = tid >> 2, kc0 = (tid & 3) * 2;
    const float* bsrc = g_wout_t + ((size_t)e * D_DIM + n0 + bn) * F_DIM + kc0 * 4;

    uint32_t aoff = (uint32_t)(((lane & 7) + ((lane >> 4) & 1) * 8) * (LDA * 4)
                               + ((lane >> 3) & 1) * 16);

    float c[2][4][4];
#pragma unroll
    for (int mi = 0; mi < 2; mi++)
#pragma unroll
        for (int ni = 0; ni < 4; ni++)
#pragma unroll
            for (int j = 0; j < 4; j++) c[mi][ni][j] = 0.f;

    auto issue = [&](int it) {
        char* sA = dynsmem + (it % NSTAGE) * STAGE2;
        char* sB = sA + A_BYTES;
        int k0 = it * 32;
        uint32_t da = s2u(sA) + rowA * (LDA * 4) + ac * 16;
#pragma unroll
        for (int i = 0; i < 4; i++)
            cpa16(da + i * 16, asrc + k0 + i * 4, 16);
        uint32_t db = s2u(sB) + bn * (LDA * 4) + kc0 * 16;
#pragma unroll
        for (int i = 0; i < 2; i++)
            cpa16(db + i * 16, bsrc + k0 + i * 4, 16);
        CP_COMMIT();
    };

    issue(0);
    issue(1);

    for (int it = 0; it < NS2; it++) {
        if (it + 2 < NS2) { issue(it + 2); CP_WAIT2(); }
        else if (it + 1 < NS2) { CP_WAIT1(); }
        else { CP_WAIT0(); }
        __syncthreads();

        char* sA = dynsmem + (it % NSTAGE) * STAGE2;
        char* sB = sA + A_BYTES;
        uint32_t aA = s2u(sA) + (uint32_t)(wm * 32 * (LDA * 4)) + aoff;
        uint32_t aB = s2u(sB) + (uint32_t)(wn * 32 * (LDA * 4)) + aoff;
#pragma unroll
        for (int kb = 0; kb < 4; kb++) {
            uint32_t koff = kb * 32;
            uint32_t a[2][4], f[2][4];
            ldsmA(a[0], aA + koff);
            ldsmA(a[1], aA + 16 * (LDA * 4) + koff);
            ldsm4(f[0], aB + koff);
            ldsm4(f[1], aB + 16 * (LDA * 4) + koff);
#pragma unroll
            for (int mi = 0; mi < 2; mi++)
#pragma unroll
                for (int j = 0; j < 2; j++) {
                    mma_tf32(c[mi][2 * j],     a[mi], &f[j][0]);
                    mma_tf32(c[mi][2 * j + 1], a[mi], &f[j][2]);
                }
        }
        __syncthreads();
    }

    // epilogue: gate-weighted atomic accumulate
#pragma unroll
    for (int mi = 0; mi < 2; mi++) {
#pragma unroll
        for (int ni = 0; ni < 4; ni++) {
            int col = n0 + wn * 32 + ni * 8 + t4 * 2;
            float b0 = bout[e * D_DIM + col], b1 = bout[e * D_DIM + col + 1];
#pragma unroll
            for (int h = 0; h < 2; h++) {
                int rowp = row0 + wm * 32 + mi * 16 + g4 + h * 8;
                int tok = g_pair_token[rowp];
                if (tok >= 0) {
                    float w = g_pair_w[rowp];
                    atomicAdd(&out[(size_t)tok * D_DIM + col],     w * (c[mi][ni][h * 2 + 0] + b0));
                    atomicAdd(&out[(size_t)tok * D_DIM + col + 1], w * (c[mi][ni][h * 2 + 1] + b1));
                }
            }
        }
    }
}

// ---------------------------------------------------------------------------
extern "C" void kernel_launch(void* const* d_in, const int* in_sizes, int n_in,
                              void* d_out, int out_size) {
    const float* states = (const float*)d_in[0];
    const float* Wg     = (const float*)d_in[1];
    const float* Win    = (const float*)d_in[2];
    const float* bin    = (const float*)d_in[3];
    const float* Wsc    = (const float*)d_in[4];
    const float* bsc    = (const float*)d_in[5];
    const float* Wout   = (const float*)d_in[6];
    const float* bout   = (const float*)d_in[7];
    float* out = (float*)d_out;

    cudaFuncSetAttribute(gemm1_kernel, cudaFuncAttributeMaxDynamicSharedMemorySize, SMEM1);
    cudaFuncSetAttribute(gemm2_kernel, cudaFuncAttributeMaxDynamicSharedMemorySize, SMEM2);

    init_kernel<<<(out_size + 255) / 256, 256>>>(out, out_size);
    router_kernel<<<N_TOK / 8, 256>>>(states, Wg);
    setup_kernel<<<1, 32>>>();
    scatter_kernel<<<(NPAIR + 255) / 256, 256>>>();
    convert_x_kernel<<<(N_TOK * D_DIM / 4 + 255) / 256, 256>>>(states);
    transpose_w_kernel<<<dim3(F_DIM / 32, D_DIM / 32, E_NUM), 256>>>(Win,  0, D_DIM, F_DIM);
    transpose_w_kernel<<<dim3(F_DIM / 32, D_DIM / 32, E_NUM), 256>>>(Wsc,  1, D_DIM, F_DIM);
    transpose_w_kernel<<<dim3(D_DIM / 32, F_DIM / 32, E_NUM), 256>>>(Wout, 2, F_DIM, D_DIM);
    gemm1_kernel<<<dim3(F_DIM / 64, MAXTILES), 256, SMEM1>>>(bin, bsc);
    gemm2_kernel<<<dim3(D_DIM / 64, MAXTILES), 256, SMEM2>>>(bout, out);
}

// round 14
// speedup vs baseline: 2.2625x; 1.7114x over previous
#include <cuda_runtime.h>
#include <cuda_fp16.h>
#include <math.h>
#include <stdint.h>

// Problem constants (fixed by the dataset)
#define D_DIM   1024
#define F_DIM   2048
#define E_NUM   8
#define N_TOK   2048
#define NPAIR   4096
#define PADROWS 5120
#define MAXTILES 40
#define NS1 16            // 1024/64 K-stages, GEMM1 (BK=64 fp16)
#define NS2 32            // 2048/64 K-stages, GEMM2
#define ROWB 144          // smem row stride bytes: 64 fp16 (128B) + 16B pad

#define A_BYTES  (128 * ROWB)             // 18432
#define B_BYTES  (64 * ROWB)              // 9216
#define STAGE1   (A_BYTES + 2 * B_BYTES)  // 36864
#define STAGE2   (A_BYTES + B_BYTES)      // 27648
#define NSTAGE   3
#define SMEM1    (NSTAGE * STAGE1)        // 110592
#define SMEM2    (NSTAGE * STAGE2)        // 82944

// Scratch (device globals — no runtime allocation allowed)
__device__ __align__(16) __half g_inner_h[(size_t)PADROWS * F_DIM];
__device__ __align__(16) __half g_x_h[(size_t)N_TOK * D_DIM];
__device__ __align__(16) __half g_win_h[(size_t)E_NUM * F_DIM * D_DIM];  // [e][n][k]
__device__ __align__(16) __half g_wsc_h[(size_t)E_NUM * F_DIM * D_DIM];  // [e][n][k]
__device__ __align__(16) __half g_wout_h[(size_t)E_NUM * D_DIM * F_DIM]; // [e][n][k]
__device__ int   g_pair_token[PADROWS];
__device__ float g_pair_w[PADROWS];
__device__ int   g_topi[N_TOK * 2];
__device__ float g_topw[N_TOK * 2];
__device__ int   g_counts[E_NUM];
__device__ int   g_cursor[E_NUM];
__device__ int   g_tile_e[MAXTILES];

__device__ __forceinline__ uint32_t s2u(const void* p) {
    return (uint32_t)__cvta_generic_to_shared((void*)p);
}
__device__ __forceinline__ void cpa16(uint32_t dst, const void* src, uint32_t sz) {
    asm volatile("cp.async.cg.shared.global [%0], [%1], 16, %2;"
                 :: "r"(dst), "l"(src), "r"(sz) : "memory");
}
#define CP_COMMIT() asm volatile("cp.async.commit_group;" ::: "memory")
#define CP_WAIT0()  asm volatile("cp.async.wait_group 0;" ::: "memory")
#define CP_WAIT1()  asm volatile("cp.async.wait_group 1;" ::: "memory")
#define CP_WAIT2()  asm volatile("cp.async.wait_group 2;" ::: "memory")

__device__ __forceinline__ void mma_f16(float c[4], const uint32_t a[4],
                                        const uint32_t b[2]) {
    asm volatile(
        "mma.sync.aligned.m16n8k16.row.col.f32.f16.f16.f32 "
        "{%0,%1,%2,%3}, {%4,%5,%6,%7}, {%8,%9}, {%0,%1,%2,%3};\n"
        : "+f"(c[0]), "+f"(c[1]), "+f"(c[2]), "+f"(c[3])
        : "r"(a[0]), "r"(a[1]), "r"(a[2]), "r"(a[3]), "r"(b[0]), "r"(b[1]));
}
__device__ __forceinline__ void ldsm4(uint32_t r[4], uint32_t addr) {
    asm volatile("ldmatrix.sync.aligned.m8n8.x4.shared.b16 {%0,%1,%2,%3}, [%4];"
                 : "=r"(r[0]), "=r"(r[1]), "=r"(r[2]), "=r"(r[3]) : "r"(addr));
}
// With our aoff map: m0=(rows0-7,k0-7) m1=(rows0-7,k8-15) m2=(rows8-15,k0-7)
// m3=(rows8-15,k8-15). fp16 A fragment = {m0, m2, m1, m3} (verified mapping).
__device__ __forceinline__ void ldsmA(uint32_t a[4], uint32_t addr) {
    uint32_t r[4];
    ldsm4(r, addr);
    a[0] = r[0]; a[1] = r[2]; a[2] = r[1]; a[3] = r[3];
}

// ---------------------------------------------------------------------------
// small kernels
// ---------------------------------------------------------------------------
__global__ void init_kernel(float* out, int out_size) {
    int idx = blockIdx.x * blockDim.x + threadIdx.x;
    if (idx < out_size) out[idx] = 0.f;
    if (idx < PADROWS)  g_pair_token[idx] = -1;
    if (idx < E_NUM)    g_counts[idx] = 0;
}

__global__ void router_kernel(const float* __restrict__ x,
                              const float* __restrict__ Wg) {
    int warp = threadIdx.x >> 5;
    int lane = threadIdx.x & 31;
    int n = blockIdx.x * 8 + warp;
    if (n >= N_TOK) return;
    float acc[E_NUM];
#pragma unroll
    for (int e = 0; e < E_NUM; e++) acc[e] = 0.f;
    const float* xr = x + (size_t)n * D_DIM;
    for (int d = lane; d < D_DIM; d += 32) {
        float xv = xr[d];
#pragma unroll
        for (int e = 0; e < E_NUM; e++) acc[e] += xv * Wg[d * E_NUM + e];
    }
#pragma unroll
    for (int e = 0; e < E_NUM; e++) {
#pragma unroll
        for (int off = 16; off > 0; off >>= 1)
            acc[e] += __shfl_xor_sync(0xffffffffu, acc[e], off);
    }
    if (lane == 0) {
        float m = acc[0];
#pragma unroll
        for (int e = 1; e < E_NUM; e++) m = fmaxf(m, acc[e]);
        float p[E_NUM];
#pragma unroll
        for (int e = 0; e < E_NUM; e++) p[e] = expf(acc[e] - m);
        int i1 = 0;
#pragma unroll
        for (int e = 1; e < E_NUM; e++) if (p[e] > p[i1]) i1 = e;
        int i2 = (i1 == 0) ? 1 : 0;
#pragma unroll
        for (int e = 0; e < E_NUM; e++)
            if (e != i1 && p[e] > p[i2]) i2 = e;
        float inv = 1.f / (p[i1] + p[i2]);
        g_topi[n * 2 + 0] = i1;  g_topw[n * 2 + 0] = p[i1] * inv;
        g_topi[n * 2 + 1] = i2;  g_topw[n * 2 + 1] = p[i2] * inv;
        atomicAdd(&g_counts[i1], 1);
        atomicAdd(&g_counts[i2], 1);
    }
}

__global__ void setup_kernel() {
    if (threadIdx.x != 0 || blockIdx.x != 0) return;
    int off = 0;
    int pad[E_NUM];
    for (int e = 0; e < E_NUM; e++) {
        g_cursor[e] = off;
        int p = ((g_counts[e] + 127) / 128) * 128;
        pad[e] = p;
        off += p;
    }
    int t = 0;
    for (int e = 0; e < E_NUM; e++)
        for (int r = 0; r < pad[e]; r += 128) g_tile_e[t++] = e;
    for (; t < MAXTILES; t++) g_tile_e[t] = -1;
}

__global__ void scatter_kernel() {
    int idx = blockIdx.x * blockDim.x + threadIdx.x;
    if (idx >= NPAIR) return;
    int e = g_topi[idx];
    int pos = atomicAdd(&g_cursor[e], 1);
    g_pair_token[pos] = idx >> 1;
    g_pair_w[pos] = g_topw[idx];
}

// ---------------------------------------------------------------------------
// converts. Destinations are __device__ globals — must be resolved in device
// code (host-side symbol decay = round-12 bug).
// ---------------------------------------------------------------------------
__global__ void convert_x_kernel(const float* __restrict__ x) {
    size_t idx = (size_t)blockIdx.x * blockDim.x + threadIdx.x;  // 8 elems each
    const float4* s = (const float4*)x + idx * 2;
    float4 v0 = s[0], v1 = s[1];
    __half2 h[4];
    h[0] = __floats2half2_rn(v0.x, v0.y);
    h[1] = __floats2half2_rn(v0.z, v0.w);
    h[2] = __floats2half2_rn(v1.x, v1.y);
    h[3] = __floats2half2_rn(v1.z, v1.w);
    *(uint4*)(g_x_h + idx * 8) = *(uint4*)h;
}

// src [e][Kd][Nd] fp32 -> dst[which] [e][Nd][Kd] fp16. Grid (Nd/32, Kd/32, E)
__global__ void transpose_w_kernel(const float* __restrict__ src, int which,
                                   int Kd, int Nd) {
    __shared__ float t[32][33];
    __half* dstg = (which == 0) ? g_win_h : (which == 1) ? g_wsc_h : g_wout_h;
    const float* s = src + (size_t)blockIdx.z * Kd * Nd;
    __half* d = dstg + (size_t)blockIdx.z * Kd * Nd;
    int n0 = blockIdx.x * 32, k0 = blockIdx.y * 32;
    int tx = threadIdx.x & 31, ty = threadIdx.x >> 5;
#pragma unroll
    for (int i = 0; i < 4; i++)
        t[ty + i * 8][tx] = s[(size_t)(k0 + ty + i * 8) * Nd + n0 + tx];
    __syncthreads();
#pragma unroll
    for (int i = 0; i < 4; i++)
        d[(size_t)(n0 + ty + i * 8) * Kd + k0 + tx] =
            __float2half_rn(t[tx][ty + i * 8]);
}

// ---------------------------------------------------------------------------
// GEMM1: inner = gelu(X@W_in + b_in) * (X@W_scale + b_scale)
// Grid (F/64, MAXTILES). fp16 m16n8k16, cp.async 3-stage, BK=64.
// ---------------------------------------------------------------------------
extern __shared__ __align__(16) char dynsmem[];

__global__ __launch_bounds__(256, 2)
void gemm1_kernel(const float* __restrict__ bin, const float* __restrict__ bsc) {
    int e = g_tile_e[blockIdx.y];
    if (e < 0) return;
    int row0 = blockIdx.y * 128;
    int n0   = blockIdx.x * 64;

    int tid = threadIdx.x;
    int lane = tid & 31, warp = tid >> 5;
    int wm = warp & 3, wn = warp >> 2;
    int g4 = lane >> 2, t4 = lane & 3;

    // A loader: row = tid>>1, 4 16B chunks; half-base hb = (tid&1)*32 halves
    int rowA = tid >> 1;
    int hb = (tid & 1) * 32;
    int tok = g_pair_token[row0 + rowA];
    uint32_t asz = (tok >= 0) ? 16u : 0u;
    const __half* asrc = g_x_h + (size_t)(tok >= 0 ? tok : 0) * D_DIM + hb;
    // B loader: n-row = tid>>2, chunks kc0, kc0+1 (16B each)
    int bn = tid >> 2, kc0 = (tid & 3) * 2;
    const __half* b1src = g_win_h + ((size_t)e * F_DIM + n0 + bn) * D_DIM + kc0 * 8;
    const __half* b2src = g_wsc_h + ((size_t)e * F_DIM + n0 + bn) * D_DIM + kc0 * 8;

    // ldmatrix lane->addr: lanes 0-7 rows0-7 k-lo; 8-15 rows0-7 k-hi(+16B);
    // 16-23 rows8-15 k-lo; 24-31 rows8-15 k-hi.
    uint32_t aoff = (uint32_t)(((lane & 7) + ((lane >> 4) & 1) * 8) * ROWB
                               + ((lane >> 3) & 1) * 16);

    float cH[2][4][4], cS[2][4][4];
#pragma unroll
    for (int mi = 0; mi < 2; mi++)
#pragma unroll
        for (int ni = 0; ni < 4; ni++)
#pragma unroll
            for (int j = 0; j < 4; j++) { cH[mi][ni][j] = 0.f; cS[mi][ni][j] = 0.f; }

    auto issue = [&](int it) {
        char* sA  = dynsmem + (it % NSTAGE) * STAGE1;
        char* sB1 = sA + A_BYTES;
        char* sB2 = sB1 + B_BYTES;
        int k0 = it * 64;   // halves
        uint32_t da = s2u(sA) + rowA * ROWB + (tid & 1) * 64;
#pragma unroll
        for (int i = 0; i < 4; i++)
            cpa16(da + i * 16, asrc + k0 + i * 8, asz);
        uint32_t db1 = s2u(sB1) + bn * ROWB + kc0 * 16;
        uint32_t db2 = s2u(sB2) + bn * ROWB + kc0 * 16;
#pragma unroll
        for (int i = 0; i < 2; i++) {
            cpa16(db1 + i * 16, b1src + k0 + i * 8, 16);
            cpa16(db2 + i * 16, b2src + k0 + i * 8, 16);
        }
        CP_COMMIT();
    };

    issue(0);
    issue(1);

    for (int it = 0; it < NS1; it++) {
        if (it + 2 < NS1) { issue(it + 2); CP_WAIT2(); }
        else if (it + 1 < NS1) { CP_WAIT1(); }
        else { CP_WAIT0(); }
        __syncthreads();

        char* sA  = dynsmem + (it % NSTAGE) * STAGE1;
        char* sB1 = sA + A_BYTES;
        char* sB2 = sB1 + B_BYTES;
        uint32_t aA  = s2u(sA)  + (uint32_t)(wm * 32 * ROWB) + aoff;
        uint32_t aB1 = s2u(sB1) + (uint32_t)(wn * 32 * ROWB) + aoff;
        uint32_t aB2 = s2u(sB2) + (uint32_t)(wn * 32 * ROWB) + aoff;
#pragma unroll
        for (int kb = 0; kb < 4; kb++) {
            uint32_t koff = kb * 32;   // 16 halves per kb
            uint32_t a[2][4], f1[2][4], f2[2][4];
            ldsmA(a[0], aA + koff);
            ldsmA(a[1], aA + 16 * ROWB + koff);
            ldsm4(f1[0], aB1 + koff);
            ldsm4(f1[1], aB1 + 16 * ROWB + koff);
            ldsm4(f2[0], aB2 + koff);
            ldsm4(f2[1], aB2 + 16 * ROWB + koff);
#pragma unroll
            for (int mi = 0; mi < 2; mi++)
#pragma unroll
                for (int j = 0; j < 2; j++) {
                    mma_f16(cH[mi][2 * j],     a[mi], &f1[j][0]);
                    mma_f16(cH[mi][2 * j + 1], a[mi], &f1[j][2]);
                    mma_f16(cS[mi][2 * j],     a[mi], &f2[j][0]);
                    mma_f16(cS[mi][2 * j + 1], a[mi], &f2[j][2]);
                }
        }
        __syncthreads();
    }

    // epilogue: exact GELU gate, fp16 store
#pragma unroll
    for (int mi = 0; mi < 2; mi++) {
#pragma unroll
        for (int ni = 0; ni < 4; ni++) {
            int col = n0 + wn * 32 + ni * 8 + t4 * 2;
            float bi0 = bin[e * F_DIM + col], bi1 = bin[e * F_DIM + col + 1];
            float bs0 = bsc[e * F_DIM + col], bs1 = bsc[e * F_DIM + col + 1];
#pragma unroll
            for (int h = 0; h < 2; h++) {
                int row = row0 + wm * 32 + mi * 16 + g4 + h * 8;
                float h0 = cH[mi][ni][h * 2 + 0] + bi0;
                float h1 = cH[mi][ni][h * 2 + 1] + bi1;
                float s0 = cS[mi][ni][h * 2 + 0] + bs0;
                float s1 = cS[mi][ni][h * 2 + 1] + bs1;
                float gl0 = 0.5f * h0 * (1.f + erff(h0 * 0.70710678118654752f));
                float gl1 = 0.5f * h1 * (1.f + erff(h1 * 0.70710678118654752f));
                *(__half2*)(g_inner_h + (size_t)row * F_DIM + col) =
                    __floats2half2_rn(gl0 * s0, gl1 * s1);
            }
        }
    }
}

// ---------------------------------------------------------------------------
// GEMM2: y = inner @ W_out + b_out; out[token] += gate * y (atomic)
// Grid (D/64, MAXTILES)
// ---------------------------------------------------------------------------
__global__ __launch_bounds__(256, 2)
void gemm2_kernel(const float* __restrict__ bout, float* __restrict__ out) {
    int e = g_tile_e[blockIdx.y];
    if (e < 0) return;
    int row0 = blockIdx.y * 128;
    int n0   = blockIdx.x * 64;

    int tid = threadIdx.x;
    int lane = tid & 31, warp = tid >> 5;
    int wm = warp & 3, wn = warp >> 2;
    int g4 = lane >> 2, t4 = lane & 3;

    int rowA = tid >> 1;
    int hb = (tid & 1) * 32;
    const __half* asrc = g_inner_h + (size_t)(row0 + rowA) * F_DIM + hb;
    int bn = tid >> 2, kc0 = (tid & 3) * 2;
    const __half* bsrc = g_wout_h + ((size_t)e * D_DIM + n0 + bn) * F_DIM + kc0 * 8;

    uint32_t aoff = (uint32_t)(((lane & 7) + ((lane >> 4) & 1) * 8) * ROWB
                               + ((lane >> 3) & 1) * 16);

    float c[2][4][4];
#pragma unroll
    for (int mi = 0; mi < 2; mi++)
#pragma unroll
        for (int ni = 0; ni < 4; ni++)
#pragma unroll
            for (int j = 0; j < 4; j++) c[mi][ni][j] = 0.f;

    auto issue = [&](int it) {
        char* sA = dynsmem + (it % NSTAGE) * STAGE2;
        char* sB = sA + A_BYTES;
        int k0 = it * 64;
        uint32_t da = s2u(sA) + rowA * ROWB + (tid & 1) * 64;
#pragma unroll
        for (int i = 0; i < 4; i++)
            cpa16(da + i * 16, asrc + k0 + i * 8, 16);
        uint32_t db = s2u(sB) + bn * ROWB + kc0 * 16;
#pragma unroll
        for (int i = 0; i < 2; i++)
            cpa16(db + i * 16, bsrc + k0 + i * 8, 16);
        CP_COMMIT();
    };

    issue(0);
    issue(1);

    for (int it = 0; it < NS2; it++) {
        if (it + 2 < NS2) { issue(it + 2); CP_WAIT2(); }
        else if (it + 1 < NS2) { CP_WAIT1(); }
        else { CP_WAIT0(); }
        __syncthreads();

        char* sA = dynsmem + (it % NSTAGE) * STAGE2;
        char* sB = sA + A_BYTES;
        uint32_t aA = s2u(sA) + (uint32_t)(wm * 32 * ROWB) + aoff;
        uint32_t aB = s2u(sB) + (uint32_t)(wn * 32 * ROWB) + aoff;
#pragma unroll
        for (int kb = 0; kb < 4; kb++) {
            uint32_t koff = kb * 32;
            uint32_t a[2][4], f[2][4];
            ldsmA(a[0], aA + koff);
            ldsmA(a[1], aA + 16 * ROWB + koff);
            ldsm4(f[0], aB + koff);
            ldsm4(f[1], aB + 16 * ROWB + koff);
#pragma unroll
            for (int mi = 0; mi < 2; mi++)
#pragma unroll
                for (int j = 0; j < 2; j++) {
                    mma_f16(c[mi][2 * j],     a[mi], &f[j][0]);
                    mma_f16(c[mi][2 * j + 1], a[mi], &f[j][2]);
                }
        }
        __syncthreads();
    }

    // epilogue: gate-weighted atomic accumulate
#pragma unroll
    for (int mi = 0; mi < 2; mi++) {
#pragma unroll
        for (int ni = 0; ni < 4; ni++) {
            int col = n0 + wn * 32 + ni * 8 + t4 * 2;
            float b0 = bout[e * D_DIM + col], b1 = bout[e * D_DIM + col + 1];
#pragma unroll
            for (int h = 0; h < 2; h++) {
                int rowp = row0 + wm * 32 + mi * 16 + g4 + h * 8;
                int tok = g_pair_token[rowp];
                if (tok >= 0) {
                    float w = g_pair_w[rowp];
                    atomicAdd(&out[(size_t)tok * D_DIM + col],     w * (c[mi][ni][h * 2 + 0] + b0));
                    atomicAdd(&out[(size_t)tok * D_DIM + col + 1], w * (c[mi][ni][h * 2 + 1] + b1));
                }
            }
        }
    }
}

// ---------------------------------------------------------------------------
extern "C" void kernel_launch(void* const* d_in, const int* in_sizes, int n_in,
                              void* d_out, int out_size) {
    const float* states = (const float*)d_in[0];
    const float* Wg     = (const float*)d_in[1];
    const float* Win    = (const float*)d_in[2];
    const float* bin    = (const float*)d_in[3];
    const float* Wsc    = (const float*)d_in[4];
    const float* bsc    = (const float*)d_in[5];
    const float* Wout   = (const float*)d_in[6];
    const float* bout   = (const float*)d_in[7];
    float* out = (float*)d_out;

    cudaFuncSetAttribute(gemm1_kernel, cudaFuncAttributeMaxDynamicSharedMemorySize, SMEM1);
    cudaFuncSetAttribute(gemm2_kernel, cudaFuncAttributeMaxDynamicSharedMemorySize, SMEM2);

    init_kernel<<<(out_size + 255) / 256, 256>>>(out, out_size);
    router_kernel<<<N_TOK / 8, 256>>>(states, Wg);
    setup_kernel<<<1, 32>>>();
    scatter_kernel<<<(NPAIR + 255) / 256, 256>>>();
    convert_x_kernel<<<(N_TOK * D_DIM / 8 + 255) / 256, 256>>>(states);
    transpose_w_kernel<<<dim3(F_DIM / 32, D_DIM / 32, E_NUM), 256>>>(Win,  0, D_DIM, F_DIM);
    transpose_w_kernel<<<dim3(F_DIM / 32, D_DIM / 32, E_NUM), 256>>>(Wsc,  1, D_DIM, F_DIM);
    transpose_w_kernel<<<dim3(D_DIM / 32, F_DIM / 32, E_NUM), 256>>>(Wout, 2, F_DIM, D_DIM);
    gemm1_kernel<<<dim3(F_DIM / 64, MAXTILES), 256, SMEM1>>>(bin, bsc);
    gemm2_kernel<<<dim3(D_DIM / 64, MAXTILES), 256, SMEM2>>>(bout, out);
}

// round 15
// speedup vs baseline: 2.3547x; 1.0408x over previous
#include <cuda_runtime.h>
#include <cuda_fp16.h>
#include <math.h>
#include <stdint.h>

// Problem constants (fixed by the dataset)
#define D_DIM   1024
#define F_DIM   2048
#define E_NUM   8
#define N_TOK   2048
#define NPAIR   4096
#define PADROWS 5120
#define MAXTILES 40
#define NS1 16            // 1024/64 K-stages, GEMM1 (BK=64 fp16)
#define NS2 32            // 2048/64 K-stages, GEMM2
#define ROWB 144          // smem row stride bytes: 64 fp16 (128B) + 16B pad

#define A_BYTES  (128 * ROWB)             // 18432
#define B_BYTES  (64 * ROWB)              // 9216
#define STAGE1   (A_BYTES + 2 * B_BYTES)  // 36864
#define STAGE2   (A_BYTES + B_BYTES)      // 27648
#define NSTAGE   3
#define SMEM1    (NSTAGE * STAGE1)        // 110592
#define SMEM2    (NSTAGE * STAGE2)        // 82944

// prep kernel block ranges
#define PREP_W_BLOCKS   4096              // per weight: (64x64 tiles) 512 * E
#define PREP_X_BLOCKS   1024              // 2048*1024 halves / 8 per thread / 256
#define PREP_Z_BLOCKS   20                // PADROWS/256
#define PREP_TOTAL      (3 * PREP_W_BLOCKS + PREP_X_BLOCKS + PREP_Z_BLOCKS)

// Scratch (device globals — no runtime allocation allowed)
__device__ __align__(16) __half g_inner_h[(size_t)PADROWS * F_DIM];
__device__ __align__(16) __half g_x_h[(size_t)N_TOK * D_DIM];
__device__ __align__(16) __half g_win_h[(size_t)E_NUM * F_DIM * D_DIM];  // [e][n][k]
__device__ __align__(16) __half g_wsc_h[(size_t)E_NUM * F_DIM * D_DIM];  // [e][n][k]
__device__ __align__(16) __half g_wout_h[(size_t)E_NUM * D_DIM * F_DIM]; // [e][n][k]
__device__ int   g_pair_token[PADROWS];
__device__ float g_pair_w[PADROWS];
__device__ int   g_topi[N_TOK * 2];
__device__ float g_topw[N_TOK * 2];
__device__ int   g_counts[E_NUM];
__device__ int   g_cursor[E_NUM];
__device__ int   g_tile_e[MAXTILES];

__device__ __forceinline__ uint32_t s2u(const void* p) {
    return (uint32_t)__cvta_generic_to_shared((void*)p);
}
__device__ __forceinline__ void cpa16(uint32_t dst, const void* src, uint32_t sz) {
    asm volatile("cp.async.cg.shared.global [%0], [%1], 16, %2;"
                 :: "r"(dst), "l"(src), "r"(sz) : "memory");
}
#define CP_COMMIT() asm volatile("cp.async.commit_group;" ::: "memory")
#define CP_WAIT0()  asm volatile("cp.async.wait_group 0;" ::: "memory")
#define CP_WAIT1()  asm volatile("cp.async.wait_group 1;" ::: "memory")
#define CP_WAIT2()  asm volatile("cp.async.wait_group 2;" ::: "memory")

__device__ __forceinline__ void mma_f16(float c[4], const uint32_t a[4],
                                        const uint32_t b[2]) {
    asm volatile(
        "mma.sync.aligned.m16n8k16.row.col.f32.f16.f16.f32 "
        "{%0,%1,%2,%3}, {%4,%5,%6,%7}, {%8,%9}, {%0,%1,%2,%3};\n"
        : "+f"(c[0]), "+f"(c[1]), "+f"(c[2]), "+f"(c[3])
        : "r"(a[0]), "r"(a[1]), "r"(a[2]), "r"(a[3]), "r"(b[0]), "r"(b[1]));
}
__device__ __forceinline__ void ldsm4(uint32_t r[4], uint32_t addr) {
    asm volatile("ldmatrix.sync.aligned.m8n8.x4.shared.b16 {%0,%1,%2,%3}, [%4];"
                 : "=r"(r[0]), "=r"(r[1]), "=r"(r[2]), "=r"(r[3]) : "r"(addr));
}
// fp16 A fragment = {m0, m2, m1, m3} of the x4 result (verified mapping).
__device__ __forceinline__ void ldsmA(uint32_t a[4], uint32_t addr) {
    uint32_t r[4];
    ldsm4(r, addr);
    a[0] = r[0]; a[1] = r[2]; a[2] = r[1]; a[3] = r[3];
}

// ---------------------------------------------------------------------------
// prep (launch slot 1): weight transposes (fp32 [e][K][N] -> fp16 [e][N][K]),
// x convert, pair-token poison, count zeroing. All dst are device globals,
// resolved in device code.
// ---------------------------------------------------------------------------
__device__ void transpose64(const float* __restrict__ src, __half* __restrict__ dst,
                            int Kd, int Nd, int t) {
    __shared__ float tile[64 * 66];
    int ntn = Nd / 64;
    int e = t >> 9;                 // 512 tiles per expert (both shapes)
    int rem = t & 511;
    int kt = rem / ntn, nt = rem % ntn;
    int k0 = kt * 64, n0 = nt * 64;
    int tid = threadIdx.x;

    const float* s = src + (size_t)e * Kd * Nd + (size_t)k0 * Nd + n0;
    int r = tid >> 2, c4 = tid & 3;
#pragma unroll
    for (int i = 0; i < 4; i++) {
        int c = c4 * 4 + i * 16;
        float4 v = *(const float4*)(s + (size_t)r * Nd + c);
        tile[r * 66 + c + 0] = v.x;
        tile[r * 66 + c + 1] = v.y;
        tile[r * 66 + c + 2] = v.z;
        tile[r * 66 + c + 3] = v.w;
    }
    __syncthreads();
    __half* d = dst + (size_t)e * Kd * Nd + (size_t)n0 * Kd + k0;
    int n = tid >> 2, kc = tid & 3;
#pragma unroll
    for (int i = 0; i < 4; i++) {
        int bk = (kc + i * 4) * 4;
        float f0 = tile[(bk + 0) * 66 + n];
        float f1 = tile[(bk + 1) * 66 + n];
        float f2 = tile[(bk + 2) * 66 + n];
        float f3 = tile[(bk + 3) * 66 + n];
        __half2 h01 = __floats2half2_rn(f0, f1);
        __half2 h23 = __floats2half2_rn(f2, f3);
        uint2 u = make_uint2(*(uint32_t*)&h01, *(uint32_t*)&h23);
        *(uint2*)(d + (size_t)n * Kd + bk) = u;
    }
}

__global__ void prep_kernel(const float* __restrict__ Win,
                            const float* __restrict__ Wsc,
                            const float* __restrict__ Wout,
                            const float* __restrict__ x) {
    int b = blockIdx.x;
    if (b < PREP_W_BLOCKS) {
        transpose64(Win, g_win_h, D_DIM, F_DIM, b);
    } else if (b < 2 * PREP_W_BLOCKS) {
        transpose64(Wsc, g_wsc_h, D_DIM, F_DIM, b - PREP_W_BLOCKS);
    } else if (b < 3 * PREP_W_BLOCKS) {
        transpose64(Wout, g_wout_h, F_DIM, D_DIM, b - 2 * PREP_W_BLOCKS);
    } else if (b < 3 * PREP_W_BLOCKS + PREP_X_BLOCKS) {
        size_t idx = (size_t)(b - 3 * PREP_W_BLOCKS) * 256 + threadIdx.x;
        const float4* s = (const float4*)x + idx * 2;
        float4 v0 = s[0], v1 = s[1];
        __half2 h[4];
        h[0] = __floats2half2_rn(v0.x, v0.y);
        h[1] = __floats2half2_rn(v0.z, v0.w);
        h[2] = __floats2half2_rn(v1.x, v1.y);
        h[3] = __floats2half2_rn(v1.z, v1.w);
        *(uint4*)(g_x_h + idx * 8) = *(uint4*)h;
    } else {
        int i = (b - 3 * PREP_W_BLOCKS - PREP_X_BLOCKS) * 256 + threadIdx.x;
        if (i < PADROWS) g_pair_token[i] = -1;
        if (i < E_NUM)   g_counts[i] = 0;
    }
}

// ---------------------------------------------------------------------------
// router (slot 2): top-2 gating; also zeroes `out` (grid-stride float4)
// ---------------------------------------------------------------------------
__global__ void router_kernel(const float* __restrict__ x,
                              const float* __restrict__ Wg,
                              float* __restrict__ out, int out_q) {
    // zero out (out_q = out_size/4 float4s); 65536 threads total
    float4 z = make_float4(0.f, 0.f, 0.f, 0.f);
    for (int i = blockIdx.x * 256 + threadIdx.x; i < out_q; i += 65536)
        ((float4*)out)[i] = z;

    int warp = threadIdx.x >> 5;
    int lane = threadIdx.x & 31;
    int n = blockIdx.x * 8 + warp;
    if (n >= N_TOK) return;
    float acc[E_NUM];
#pragma unroll
    for (int e = 0; e < E_NUM; e++) acc[e] = 0.f;
    const float* xr = x + (size_t)n * D_DIM;
    for (int d = lane; d < D_DIM; d += 32) {
        float xv = xr[d];
#pragma unroll
        for (int e = 0; e < E_NUM; e++) acc[e] += xv * Wg[d * E_NUM + e];
    }
#pragma unroll
    for (int e = 0; e < E_NUM; e++) {
#pragma unroll
        for (int off = 16; off > 0; off >>= 1)
            acc[e] += __shfl_xor_sync(0xffffffffu, acc[e], off);
    }
    if (lane == 0) {
        float m = acc[0];
#pragma unroll
        for (int e = 1; e < E_NUM; e++) m = fmaxf(m, acc[e]);
        float p[E_NUM];
#pragma unroll
        for (int e = 0; e < E_NUM; e++) p[e] = expf(acc[e] - m);
        int i1 = 0;
#pragma unroll
        for (int e = 1; e < E_NUM; e++) if (p[e] > p[i1]) i1 = e;
        int i2 = (i1 == 0) ? 1 : 0;
#pragma unroll
        for (int e = 0; e < E_NUM; e++)
            if (e != i1 && p[e] > p[i2]) i2 = e;
        float inv = 1.f / (p[i1] + p[i2]);
        g_topi[n * 2 + 0] = i1;  g_topw[n * 2 + 0] = p[i1] * inv;
        g_topi[n * 2 + 1] = i2;  g_topw[n * 2 + 1] = p[i2] * inv;
        atomicAdd(&g_counts[i1], 1);
        atomicAdd(&g_counts[i2], 1);
    }
}

// ---------------------------------------------------------------------------
// scatter (slot 3): single block; fused setup (prefix sums + tile map)
// ---------------------------------------------------------------------------
__global__ void scatter_kernel() {
    if (threadIdx.x == 0) {
        int off = 0;
        int pad[E_NUM];
        for (int e = 0; e < E_NUM; e++) {
            g_cursor[e] = off;
            int p = ((g_counts[e] + 127) / 128) * 128;
            pad[e] = p;
            off += p;
        }
        int t = 0;
        for (int e = 0; e < E_NUM; e++)
            for (int r = 0; r < pad[e]; r += 128) g_tile_e[t++] = e;
        for (; t < MAXTILES; t++) g_tile_e[t] = -1;
    }
    __syncthreads();
    for (int idx = threadIdx.x; idx < NPAIR; idx += 256) {
        int e = g_topi[idx];
        int pos = atomicAdd(&g_cursor[e], 1);
        g_pair_token[pos] = idx >> 1;
        g_pair_w[pos] = g_topw[idx];
    }
}

// ---------------------------------------------------------------------------
// GEMM1 (slot 4 — profiled): inner = gelu(X@W_in + b_in) * (X@W_scale + b_scale)
// Grid (F/64, MAXTILES). fp16 m16n8k16, cp.async 3-stage, BK=64.
// ---------------------------------------------------------------------------
extern __shared__ __align__(16) char dynsmem[];

__global__ __launch_bounds__(256, 2)
void gemm1_kernel(const float* __restrict__ bin, const float* __restrict__ bsc) {
    int e = g_tile_e[blockIdx.y];
    if (e < 0) return;
    int row0 = blockIdx.y * 128;
    int n0   = blockIdx.x * 64;

    int tid = threadIdx.x;
    int lane = tid & 31, warp = tid >> 5;
    int wm = warp & 3, wn = warp >> 2;
    int g4 = lane >> 2, t4 = lane & 3;

    int rowA = tid >> 1;
    int hb = (tid & 1) * 32;
    int tok = g_pair_token[row0 + rowA];
    uint32_t asz = (tok >= 0) ? 16u : 0u;
    const __half* asrc = g_x_h + (size_t)(tok >= 0 ? tok : 0) * D_DIM + hb;
    int bn = tid >> 2, kc0 = (tid & 3) * 2;
    const __half* b1src = g_win_h + ((size_t)e * F_DIM + n0 + bn) * D_DIM + kc0 * 8;
    const __half* b2src = g_wsc_h + ((size_t)e * F_DIM + n0 + bn) * D_DIM + kc0 * 8;

    uint32_t aoff = (uint32_t)(((lane & 7) + ((lane >> 4) & 1) * 8) * ROWB
                               + ((lane >> 3) & 1) * 16);

    float cH[2][4][4], cS[2][4][4];
#pragma unroll
    for (int mi = 0; mi < 2; mi++)
#pragma unroll
        for (int ni = 0; ni < 4; ni++)
#pragma unroll
            for (int j = 0; j < 4; j++) { cH[mi][ni][j] = 0.f; cS[mi][ni][j] = 0.f; }

    auto issue = [&](int it) {
        char* sA  = dynsmem + (it % NSTAGE) * STAGE1;
        char* sB1 = sA + A_BYTES;
        char* sB2 = sB1 + B_BYTES;
        int k0 = it * 64;
        uint32_t da = s2u(sA) + rowA * ROWB + (tid & 1) * 64;
#pragma unroll
        for (int i = 0; i < 4; i++)
            cpa16(da + i * 16, asrc + k0 + i * 8, asz);
        uint32_t db1 = s2u(sB1) + bn * ROWB + kc0 * 16;
        uint32_t db2 = s2u(sB2) + bn * ROWB + kc0 * 16;
#pragma unroll
        for (int i = 0; i < 2; i++) {
            cpa16(db1 + i * 16, b1src + k0 + i * 8, 16);
            cpa16(db2 + i * 16, b2src + k0 + i * 8, 16);
        }
        CP_COMMIT();
    };

    issue(0);
    issue(1);

    for (int it = 0; it < NS1; it++) {
        if (it + 2 < NS1) { issue(it + 2); CP_WAIT2(); }
        else if (it + 1 < NS1) { CP_WAIT1(); }
        else { CP_WAIT0(); }
        __syncthreads();

        char* sA  = dynsmem + (it % NSTAGE) * STAGE1;
        char* sB1 = sA + A_BYTES;
        char* sB2 = sB1 + B_BYTES;
        uint32_t aA  = s2u(sA)  + (uint32_t)(wm * 32 * ROWB) + aoff;
        uint32_t aB1 = s2u(sB1) + (uint32_t)(wn * 32 * ROWB) + aoff;
        uint32_t aB2 = s2u(sB2) + (uint32_t)(wn * 32 * ROWB) + aoff;
#pragma unroll
        for (int kb = 0; kb < 4; kb++) {
            uint32_t koff = kb * 32;
            uint32_t a[2][4], f1[2][4], f2[2][4];
            ldsmA(a[0], aA + koff);
            ldsmA(a[1], aA + 16 * ROWB + koff);
            ldsm4(f1[0], aB1 + koff);
            ldsm4(f1[1], aB1 + 16 * ROWB + koff);
            ldsm4(f2[0], aB2 + koff);
            ldsm4(f2[1], aB2 + 16 * ROWB + koff);
#pragma unroll
            for (int mi = 0; mi < 2; mi++)
#pragma unroll
                for (int j = 0; j < 2; j++) {
                    mma_f16(cH[mi][2 * j],     a[mi], &f1[j][0]);
                    mma_f16(cH[mi][2 * j + 1], a[mi], &f1[j][2]);
                    mma_f16(cS[mi][2 * j],     a[mi], &f2[j][0]);
                    mma_f16(cS[mi][2 * j + 1], a[mi], &f2[j][2]);
                }
        }
        __syncthreads();
    }

#pragma unroll
    for (int mi = 0; mi < 2; mi++) {
#pragma unroll
        for (int ni = 0; ni < 4; ni++) {
            int col = n0 + wn * 32 + ni * 8 + t4 * 2;
            float bi0 = bin[e * F_DIM + col], bi1 = bin[e * F_DIM + col + 1];
            float bs0 = bsc[e * F_DIM + col], bs1 = bsc[e * F_DIM + col + 1];
#pragma unroll
            for (int h = 0; h < 2; h++) {
                int row = row0 + wm * 32 + mi * 16 + g4 + h * 8;
                float h0 = cH[mi][ni][h * 2 + 0] + bi0;
                float h1 = cH[mi][ni][h * 2 + 1] + bi1;
                float s0 = cS[mi][ni][h * 2 + 0] + bs0;
                float s1 = cS[mi][ni][h * 2 + 1] + bs1;
                float gl0 = 0.5f * h0 * (1.f + erff(h0 * 0.70710678118654752f));
                float gl1 = 0.5f * h1 * (1.f + erff(h1 * 0.70710678118654752f));
                *(__half2*)(g_inner_h + (size_t)row * F_DIM + col) =
                    __floats2half2_rn(gl0 * s0, gl1 * s1);
            }
        }
    }
}

// ---------------------------------------------------------------------------
// GEMM2 (slot 5): y = inner @ W_out + b_out; out[token] += gate * y (atomic)
// Grid (D/64, MAXTILES)
// ---------------------------------------------------------------------------
__global__ __launch_bounds__(256, 2)
void gemm2_kernel(const float* __restrict__ bout, float* __restrict__ out) {
    int e = g_tile_e[blockIdx.y];
    if (e < 0) return;
    int row0 = blockIdx.y * 128;
    int n0   = blockIdx.x * 64;

    int tid = threadIdx.x;
    int lane = tid & 31, warp = tid >> 5;
    int wm = warp & 3, wn = warp >> 2;
    int g4 = lane >> 2, t4 = lane & 3;

    int rowA = tid >> 1;
    int hb = (tid & 1) * 32;
    const __half* asrc = g_inner_h + (size_t)(row0 + rowA) * F_DIM + hb;
    int bn = tid >> 2, kc0 = (tid & 3) * 2;
    const __half* bsrc = g_wout_h + ((size_t)e * D_DIM + n0 + bn) * F_DIM + kc0 * 8;

    uint32_t aoff = (uint32_t)(((lane & 7) + ((lane >> 4) & 1) * 8) * ROWB
                               + ((lane >> 3) & 1) * 16);

    float c[2][4][4];
#pragma unroll
    for (int mi = 0; mi < 2; mi++)
#pragma unroll
        for (int ni = 0; ni < 4; ni++)
#pragma unroll
            for (int j = 0; j < 4; j++) c[mi][ni][j] = 0.f;

    auto issue = [&](int it) {
        char* sA = dynsmem + (it % NSTAGE) * STAGE2;
        char* sB = sA + A_BYTES;
        int k0 = it * 64;
        uint32_t da = s2u(sA) + rowA * ROWB + (tid & 1) * 64;
#pragma unroll
        for (int i = 0; i < 4; i++)
            cpa16(da + i * 16, asrc + k0 + i * 8, 16);
        uint32_t db = s2u(sB) + bn * ROWB + kc0 * 16;
#pragma unroll
        for (int i = 0; i < 2; i++)
            cpa16(db + i * 16, bsrc + k0 + i * 8, 16);
        CP_COMMIT();
    };

    issue(0);
    issue(1);

    for (int it = 0; it < NS2; it++) {
        if (it + 2 < NS2) { issue(it + 2); CP_WAIT2(); }
        else if (it + 1 < NS2) { CP_WAIT1(); }
        else { CP_WAIT0(); }
        __syncthreads();

        char* sA = dynsmem + (it % NSTAGE) * STAGE2;
        char* sB = sA + A_BYTES;
        uint32_t aA = s2u(sA) + (uint32_t)(wm * 32 * ROWB) + aoff;
        uint32_t aB = s2u(sB) + (uint32_t)(wn * 32 * ROWB) + aoff;
#pragma unroll
        for (int kb = 0; kb < 4; kb++) {
            uint32_t koff = kb * 32;
            uint32_t a[2][4], f[2][4];
            ldsmA(a[0], aA + koff);
            ldsmA(a[1], aA + 16 * ROWB + koff);
            ldsm4(f[0], aB + koff);
            ldsm4(f[1], aB + 16 * ROWB + koff);
#pragma unroll
            for (int mi = 0; mi < 2; mi++)
#pragma unroll
                for (int j = 0; j < 2; j++) {
                    mma_f16(c[mi][2 * j],     a[mi], &f[j][0]);
                    mma_f16(c[mi][2 * j + 1], a[mi], &f[j][2]);
                }
        }
        __syncthreads();
    }

#pragma unroll
    for (int mi = 0; mi < 2; mi++) {
#pragma unroll
        for (int ni = 0; ni < 4; ni++) {
            int col = n0 + wn * 32 + ni * 8 + t4 * 2;
            float b0 = bout[e * D_DIM + col], b1 = bout[e * D_DIM + col + 1];
#pragma unroll
            for (int h = 0; h < 2; h++) {
                int rowp = row0 + wm * 32 + mi * 16 + g4 + h * 8;
                int tok = g_pair_token[rowp];
                if (tok >= 0) {
                    float w = g_pair_w[rowp];
                    atomicAdd(&out[(size_t)tok * D_DIM + col],     w * (c[mi][ni][h * 2 + 0] + b0));
                    atomicAdd(&out[(size_t)tok * D_DIM + col + 1], w * (c[mi][ni][h * 2 + 1] + b1));
                }
            }
        }
    }
}

// ---------------------------------------------------------------------------
extern "C" void kernel_launch(void* const* d_in, const int* in_sizes, int n_in,
                              void* d_out, int out_size) {
    const float* states = (const float*)d_in[0];
    const float* Wg     = (const float*)d_in[1];
    const float* Win    = (const float*)d_in[2];
    const float* bin    = (const float*)d_in[3];
    const float* Wsc    = (const float*)d_in[4];
    const float* bsc    = (const float*)d_in[5];
    const float* Wout   = (const float*)d_in[6];
    const float* bout   = (const float*)d_in[7];
    float* out = (float*)d_out;

    cudaFuncSetAttribute(gemm1_kernel, cudaFuncAttributeMaxDynamicSharedMemorySize, SMEM1);
    cudaFuncSetAttribute(gemm2_kernel, cudaFuncAttributeMaxDynamicSharedMemorySize, SMEM2);

    prep_kernel<<<PREP_TOTAL, 256>>>(Win, Wsc, Wout, states);
    router_kernel<<<N_TOK / 8, 256>>>(states, Wg, out, out_size / 4);
    scatter_kernel<<<1, 256>>>();
    gemm1_kernel<<<dim3(F_DIM / 64, MAXTILES), 256, SMEM1>>>(bin, bsc);
    gemm2_kernel<<<dim3(D_DIM / 64, MAXTILES), 256, SMEM2>>>(bout, out);
}

// round 16
// speedup vs baseline: 2.7005x; 1.1468x over previous
#include <cuda_runtime.h>
#include <cuda_fp16.h>
#include <math.h>
#include <stdint.h>

// Problem constants (fixed by the dataset)
#define D_DIM   1024
#define F_DIM   2048
#define E_NUM   8
#define N_TOK   2048
#define NPAIR   4096
#define PADROWS 5120
#define MAXTILES 40
#define NS1 16            // 1024/64 K-stages, GEMM1 (BK=64 fp16)
#define NS2 32            // 2048/64 K-stages, GEMM2
#define ROWB 144          // smem row stride bytes: 64 fp16 (128B) + 16B pad

#define A_BYTES  (128 * ROWB)             // 18432
#define B_BYTES  (64 * ROWB)              // 9216
#define STAGE1   (A_BYTES + 2 * B_BYTES)  // 36864
#define STAGE2   (A_BYTES + B_BYTES)      // 27648
#define NSTAGE   3
#define SMEM1    (NSTAGE * STAGE1)        // 110592
#define SMEM2    (NSTAGE * STAGE2)        // 82944

// prep kernel block ranges
#define PREP_W_BLOCKS   4096
#define PREP_X_BLOCKS   1024
#define PREP_Z_BLOCKS   20
#define PREP_TOTAL      (3 * PREP_W_BLOCKS + PREP_X_BLOCKS + PREP_Z_BLOCKS)

// Scratch (device globals — no runtime allocation allowed)
__device__ __align__(16) __half g_inner_h[(size_t)PADROWS * F_DIM];
__device__ __align__(16) __half g_x_h[(size_t)N_TOK * D_DIM];
__device__ __align__(16) __half g_win_h[(size_t)E_NUM * F_DIM * D_DIM];  // [e][n][k]
__device__ __align__(16) __half g_wsc_h[(size_t)E_NUM * F_DIM * D_DIM];  // [e][n][k]
__device__ __align__(16) __half g_wout_h[(size_t)E_NUM * D_DIM * F_DIM]; // [e][n][k]
__device__ int   g_pair_token[PADROWS];
__device__ float g_pair_w[PADROWS];
__device__ int   g_topi[N_TOK * 2];
__device__ float g_topw[N_TOK * 2];
__device__ int   g_counts[E_NUM];
__device__ int   g_cursor[E_NUM];
__device__ int   g_tile_e[MAXTILES];

__device__ __forceinline__ uint32_t s2u(const void* p) {
    return (uint32_t)__cvta_generic_to_shared((void*)p);
}
__device__ __forceinline__ void cpa16(uint32_t dst, const void* src, uint32_t sz) {
    asm volatile("cp.async.cg.shared.global [%0], [%1], 16, %2;"
                 :: "r"(dst), "l"(src), "r"(sz) : "memory");
}
#define CP_COMMIT() asm volatile("cp.async.commit_group;" ::: "memory")
#define CP_WAIT0()  asm volatile("cp.async.wait_group 0;" ::: "memory")
#define CP_WAIT1()  asm volatile("cp.async.wait_group 1;" ::: "memory")
#define CP_WAIT2()  asm volatile("cp.async.wait_group 2;" ::: "memory")

__device__ __forceinline__ void mma_f16(float c[4], const uint32_t a[4],
                                        const uint32_t b[2]) {
    asm volatile(
        "mma.sync.aligned.m16n8k16.row.col.f32.f16.f16.f32 "
        "{%0,%1,%2,%3}, {%4,%5,%6,%7}, {%8,%9}, {%0,%1,%2,%3};\n"
        : "+f"(c[0]), "+f"(c[1]), "+f"(c[2]), "+f"(c[3])
        : "r"(a[0]), "r"(a[1]), "r"(a[2]), "r"(a[3]), "r"(b[0]), "r"(b[1]));
}
__device__ __forceinline__ void ldsm4(uint32_t r[4], uint32_t addr) {
    asm volatile("ldmatrix.sync.aligned.m8n8.x4.shared.b16 {%0,%1,%2,%3}, [%4];"
                 : "=r"(r[0]), "=r"(r[1]), "=r"(r[2]), "=r"(r[3]) : "r"(addr));
}
// fp16 A fragment = {m0, m2, m1, m3} of the x4 result (verified mapping).
__device__ __forceinline__ void ldsmA(uint32_t a[4], uint32_t addr) {
    uint32_t r[4];
    ldsm4(r, addr);
    a[0] = r[0]; a[1] = r[2]; a[2] = r[1]; a[3] = r[3];
}

// ---------------------------------------------------------------------------
// prep (slot 1): weight transposes + x convert + poison/zero
// ---------------------------------------------------------------------------
__device__ void transpose64(const float* __restrict__ src, __half* __restrict__ dst,
                            int Kd, int Nd, int t) {
    __shared__ float tile[64 * 66];
    int ntn = Nd / 64;
    int e = t >> 9;
    int rem = t & 511;
    int kt = rem / ntn, nt = rem % ntn;
    int k0 = kt * 64, n0 = nt * 64;
    int tid = threadIdx.x;

    const float* s = src + (size_t)e * Kd * Nd + (size_t)k0 * Nd + n0;
    int r = tid >> 2, c4 = tid & 3;
#pragma unroll
    for (int i = 0; i < 4; i++) {
        int c = c4 * 4 + i * 16;
        float4 v = *(const float4*)(s + (size_t)r * Nd + c);
        tile[r * 66 + c + 0] = v.x;
        tile[r * 66 + c + 1] = v.y;
        tile[r * 66 + c + 2] = v.z;
        tile[r * 66 + c + 3] = v.w;
    }
    __syncthreads();
    __half* d = dst + (size_t)e * Kd * Nd + (size_t)n0 * Kd + k0;
    int n = tid >> 2, kc = tid & 3;
#pragma unroll
    for (int i = 0; i < 4; i++) {
        int bk = (kc + i * 4) * 4;
        float f0 = tile[(bk + 0) * 66 + n];
        float f1 = tile[(bk + 1) * 66 + n];
        float f2 = tile[(bk + 2) * 66 + n];
        float f3 = tile[(bk + 3) * 66 + n];
        __half2 h01 = __floats2half2_rn(f0, f1);
        __half2 h23 = __floats2half2_rn(f2, f3);
        uint2 u = make_uint2(*(uint32_t*)&h01, *(uint32_t*)&h23);
        *(uint2*)(d + (size_t)n * Kd + bk) = u;
    }
}

__global__ void prep_kernel(const float* __restrict__ Win,
                            const float* __restrict__ Wsc,
                            const float* __restrict__ Wout,
                            const float* __restrict__ x) {
    int b = blockIdx.x;
    if (b < PREP_W_BLOCKS) {
        transpose64(Win, g_win_h, D_DIM, F_DIM, b);
    } else if (b < 2 * PREP_W_BLOCKS) {
        transpose64(Wsc, g_wsc_h, D_DIM, F_DIM, b - PREP_W_BLOCKS);
    } else if (b < 3 * PREP_W_BLOCKS) {
        transpose64(Wout, g_wout_h, F_DIM, D_DIM, b - 2 * PREP_W_BLOCKS);
    } else if (b < 3 * PREP_W_BLOCKS + PREP_X_BLOCKS) {
        size_t idx = (size_t)(b - 3 * PREP_W_BLOCKS) * 256 + threadIdx.x;
        const float4* s = (const float4*)x + idx * 2;
        float4 v0 = s[0], v1 = s[1];
        __half2 h[4];
        h[0] = __floats2half2_rn(v0.x, v0.y);
        h[1] = __floats2half2_rn(v0.z, v0.w);
        h[2] = __floats2half2_rn(v1.x, v1.y);
        h[3] = __floats2half2_rn(v1.z, v1.w);
        *(uint4*)(g_x_h + idx * 8) = *(uint4*)h;
    } else {
        int i = (b - 3 * PREP_W_BLOCKS - PREP_X_BLOCKS) * 256 + threadIdx.x;
        if (i < PADROWS) g_pair_token[i] = -1;
        if (i < E_NUM)   g_counts[i] = 0;
    }
}

// ---------------------------------------------------------------------------
// router (slot 2): top-2 gating; also zeroes `out`
// ---------------------------------------------------------------------------
__global__ void router_kernel(const float* __restrict__ x,
                              const float* __restrict__ Wg,
                              float* __restrict__ out, int out_q) {
    float4 z = make_float4(0.f, 0.f, 0.f, 0.f);
    for (int i = blockIdx.x * 256 + threadIdx.x; i < out_q; i += 65536)
        ((float4*)out)[i] = z;

    int warp = threadIdx.x >> 5;
    int lane = threadIdx.x & 31;
    int n = blockIdx.x * 8 + warp;
    if (n >= N_TOK) return;
    float acc[E_NUM];
#pragma unroll
    for (int e = 0; e < E_NUM; e++) acc[e] = 0.f;
    const float* xr = x + (size_t)n * D_DIM;
    for (int d = lane; d < D_DIM; d += 32) {
        float xv = xr[d];
#pragma unroll
        for (int e = 0; e < E_NUM; e++) acc[e] += xv * Wg[d * E_NUM + e];
    }
#pragma unroll
    for (int e = 0; e < E_NUM; e++) {
#pragma unroll
        for (int off = 16; off > 0; off >>= 1)
            acc[e] += __shfl_xor_sync(0xffffffffu, acc[e], off);
    }
    if (lane == 0) {
        float m = acc[0];
#pragma unroll
        for (int e = 1; e < E_NUM; e++) m = fmaxf(m, acc[e]);
        float p[E_NUM];
#pragma unroll
        for (int e = 0; e < E_NUM; e++) p[e] = expf(acc[e] - m);
        int i1 = 0;
#pragma unroll
        for (int e = 1; e < E_NUM; e++) if (p[e] > p[i1]) i1 = e;
        int i2 = (i1 == 0) ? 1 : 0;
#pragma unroll
        for (int e = 0; e < E_NUM; e++)
            if (e != i1 && p[e] > p[i2]) i2 = e;
        float inv = 1.f / (p[i1] + p[i2]);
        g_topi[n * 2 + 0] = i1;  g_topw[n * 2 + 0] = p[i1] * inv;
        g_topi[n * 2 + 1] = i2;  g_topw[n * 2 + 1] = p[i2] * inv;
        atomicAdd(&g_counts[i1], 1);
        atomicAdd(&g_counts[i2], 1);
    }
}

// ---------------------------------------------------------------------------
// scatter (slot 3): single block; fused setup
// ---------------------------------------------------------------------------
__global__ void scatter_kernel() {
    if (threadIdx.x == 0) {
        int off = 0;
        int pad[E_NUM];
        for (int e = 0; e < E_NUM; e++) {
            g_cursor[e] = off;
            int p = ((g_counts[e] + 127) / 128) * 128;
            pad[e] = p;
            off += p;
        }
        int t = 0;
        for (int e = 0; e < E_NUM; e++)
            for (int r = 0; r < pad[e]; r += 128) g_tile_e[t++] = e;
        for (; t < MAXTILES; t++) g_tile_e[t] = -1;
    }
    __syncthreads();
    for (int idx = threadIdx.x; idx < NPAIR; idx += 256) {
        int e = g_topi[idx];
        int pos = atomicAdd(&g_cursor[e], 1);
        g_pair_token[pos] = idx >> 1;
        g_pair_w[pos] = g_topw[idx];
    }
}

// ---------------------------------------------------------------------------
// GEMM1 (slot 4 — profiled): 512 threads, 16 warps (4m x 4n), warp tile 32x16.
// inner = gelu(X@W_in + b_in) * (X@W_scale + b_scale)
// ---------------------------------------------------------------------------
extern __shared__ __align__(16) char dynsmem[];

__global__ __launch_bounds__(512, 2)
void gemm1_kernel(const float* __restrict__ bin, const float* __restrict__ bsc) {
    int e = g_tile_e[blockIdx.y];
    if (e < 0) return;
    int row0 = blockIdx.y * 128;
    int n0   = blockIdx.x * 64;

    int tid = threadIdx.x;
    int lane = tid & 31, warp = tid >> 5;
    int wm = warp & 3, wn = warp >> 2;
    int g4 = lane >> 2, t4 = lane & 3;

    // A loader: row = tid>>2, 2 chunks (16B) at (tid&3)*2
    int rowA = tid >> 2;
    int ca = (tid & 3) * 2;
    int tok = g_pair_token[row0 + rowA];
    uint32_t asz = (tok >= 0) ? 16u : 0u;
    const __half* asrc = g_x_h + (size_t)(tok >= 0 ? tok : 0) * D_DIM + ca * 8;
    // B loader: row = tid>>3, chunk kc = tid&7
    int bn = tid >> 3, kc = tid & 7;
    const __half* b1src = g_win_h + ((size_t)e * F_DIM + n0 + bn) * D_DIM + kc * 8;
    const __half* b2src = g_wsc_h + ((size_t)e * F_DIM + n0 + bn) * D_DIM + kc * 8;

    uint32_t aoff = (uint32_t)(((lane & 7) + ((lane >> 4) & 1) * 8) * ROWB
                               + ((lane >> 3) & 1) * 16);

    float cH[2][2][4], cS[2][2][4];
#pragma unroll
    for (int mi = 0; mi < 2; mi++)
#pragma unroll
        for (int ni = 0; ni < 2; ni++)
#pragma unroll
            for (int j = 0; j < 4; j++) { cH[mi][ni][j] = 0.f; cS[mi][ni][j] = 0.f; }

    auto issue = [&](int it) {
        char* sA  = dynsmem + (it % NSTAGE) * STAGE1;
        char* sB1 = sA + A_BYTES;
        char* sB2 = sB1 + B_BYTES;
        int k0 = it * 64;
        uint32_t da = s2u(sA) + rowA * ROWB + ca * 16;
        cpa16(da,      asrc + k0,     asz);
        cpa16(da + 16, asrc + k0 + 8, asz);
        uint32_t db1 = s2u(sB1) + bn * ROWB + kc * 16;
        uint32_t db2 = s2u(sB2) + bn * ROWB + kc * 16;
        cpa16(db1, b1src + k0, 16);
        cpa16(db2, b2src + k0, 16);
        CP_COMMIT();
    };

    issue(0);
    issue(1);

    for (int it = 0; it < NS1; it++) {
        if (it + 2 < NS1) { issue(it + 2); CP_WAIT2(); }
        else if (it + 1 < NS1) { CP_WAIT1(); }
        else { CP_WAIT0(); }
        __syncthreads();

        char* sA  = dynsmem + (it % NSTAGE) * STAGE1;
        char* sB1 = sA + A_BYTES;
        char* sB2 = sB1 + B_BYTES;
        uint32_t aA  = s2u(sA)  + (uint32_t)(wm * 32 * ROWB) + aoff;
        uint32_t aB1 = s2u(sB1) + (uint32_t)(wn * 16 * ROWB) + aoff;
        uint32_t aB2 = s2u(sB2) + (uint32_t)(wn * 16 * ROWB) + aoff;
#pragma unroll
        for (int kb = 0; kb < 4; kb++) {
            uint32_t koff = kb * 32;
            uint32_t a[2][4], f1[4], f2[4];
            ldsmA(a[0], aA + koff);
            ldsmA(a[1], aA + 16 * ROWB + koff);
            ldsm4(f1, aB1 + koff);
            ldsm4(f2, aB2 + koff);
#pragma unroll
            for (int mi = 0; mi < 2; mi++) {
                mma_f16(cH[mi][0], a[mi], &f1[0]);
                mma_f16(cH[mi][1], a[mi], &f1[2]);
                mma_f16(cS[mi][0], a[mi], &f2[0]);
                mma_f16(cS[mi][1], a[mi], &f2[2]);
            }
        }
        __syncthreads();
    }

    // epilogue: exact GELU gate, fp16 store
#pragma unroll
    for (int mi = 0; mi < 2; mi++) {
#pragma unroll
        for (int ni = 0; ni < 2; ni++) {
            int col = n0 + wn * 16 + ni * 8 + t4 * 2;
            float bi0 = bin[e * F_DIM + col], bi1 = bin[e * F_DIM + col + 1];
            float bs0 = bsc[e * F_DIM + col], bs1 = bsc[e * F_DIM + col + 1];
#pragma unroll
            for (int h = 0; h < 2; h++) {
                int row = row0 + wm * 32 + mi * 16 + g4 + h * 8;
                float h0 = cH[mi][ni][h * 2 + 0] + bi0;
                float h1 = cH[mi][ni][h * 2 + 1] + bi1;
                float s0 = cS[mi][ni][h * 2 + 0] + bs0;
                float s1 = cS[mi][ni][h * 2 + 1] + bs1;
                float gl0 = 0.5f * h0 * (1.f + erff(h0 * 0.70710678118654752f));
                float gl1 = 0.5f * h1 * (1.f + erff(h1 * 0.70710678118654752f));
                *(__half2*)(g_inner_h + (size_t)row * F_DIM + col) =
                    __floats2half2_rn(gl0 * s0, gl1 * s1);
            }
        }
    }
}

// ---------------------------------------------------------------------------
// GEMM2 (slot 5): 512 threads, warp tile 32x16.
// y = inner @ W_out + b_out; out[token] += gate * y (atomic)
// ---------------------------------------------------------------------------
__global__ __launch_bounds__(512, 2)
void gemm2_kernel(const float* __restrict__ bout, float* __restrict__ out) {
    int e = g_tile_e[blockIdx.y];
    if (e < 0) return;
    int row0 = blockIdx.y * 128;
    int n0   = blockIdx.x * 64;

    int tid = threadIdx.x;
    int lane = tid & 31, warp = tid >> 5;
    int wm = warp & 3, wn = warp >> 2;
    int g4 = lane >> 2, t4 = lane & 3;

    int rowA = tid >> 2;
    int ca = (tid & 3) * 2;
    const __half* asrc = g_inner_h + (size_t)(row0 + rowA) * F_DIM + ca * 8;
    int bn = tid >> 3, kc = tid & 7;
    const __half* bsrc = g_wout_h + ((size_t)e * D_DIM + n0 + bn) * F_DIM + kc * 8;

    uint32_t aoff = (uint32_t)(((lane & 7) + ((lane >> 4) & 1) * 8) * ROWB
                               + ((lane >> 3) & 1) * 16);

    float c[2][2][4];
#pragma unroll
    for (int mi = 0; mi < 2; mi++)
#pragma unroll
        for (int ni = 0; ni < 2; ni++)
#pragma unroll
            for (int j = 0; j < 4; j++) c[mi][ni][j] = 0.f;

    auto issue = [&](int it) {
        char* sA = dynsmem + (it % NSTAGE) * STAGE2;
        char* sB = sA + A_BYTES;
        int k0 = it * 64;
        uint32_t da = s2u(sA) + rowA * ROWB + ca * 16;
        cpa16(da,      asrc + k0,     16);
        cpa16(da + 16, asrc + k0 + 8, 16);
        uint32_t db = s2u(sB) + bn * ROWB + kc * 16;
        cpa16(db, bsrc + k0, 16);
        CP_COMMIT();
    };

    issue(0);
    issue(1);

    for (int it = 0; it < NS2; it++) {
        if (it + 2 < NS2) { issue(it + 2); CP_WAIT2(); }
        else if (it + 1 < NS2) { CP_WAIT1(); }
        else { CP_WAIT0(); }
        __syncthreads();

        char* sA = dynsmem + (it % NSTAGE) * STAGE2;
        char* sB = sA + A_BYTES;
        uint32_t aA = s2u(sA) + (uint32_t)(wm * 32 * ROWB) + aoff;
        uint32_t aB = s2u(sB) + (uint32_t)(wn * 16 * ROWB) + aoff;
#pragma unroll
        for (int kb = 0; kb < 4; kb++) {
            uint32_t koff = kb * 32;
            uint32_t a[2][4], f[4];
            ldsmA(a[0], aA + koff);
            ldsmA(a[1], aA + 16 * ROWB + koff);
            ldsm4(f, aB + koff);
#pragma unroll
            for (int mi = 0; mi < 2; mi++) {
                mma_f16(c[mi][0], a[mi], &f[0]);
                mma_f16(c[mi][1], a[mi], &f[2]);
            }
        }
        __syncthreads();
    }

#pragma unroll
    for (int mi = 0; mi < 2; mi++) {
#pragma unroll
        for (int ni = 0; ni < 2; ni++) {
            int col = n0 + wn * 16 + ni * 8 + t4 * 2;
            float b0 = bout[e * D_DIM + col], b1 = bout[e * D_DIM + col + 1];
#pragma unroll
            for (int h = 0; h < 2; h++) {
                int rowp = row0 + wm * 32 + mi * 16 + g4 + h * 8;
                int tok = g_pair_token[rowp];
                if (tok >= 0) {
                    float w = g_pair_w[rowp];
                    atomicAdd(&out[(size_t)tok * D_DIM + col],     w * (c[mi][ni][h * 2 + 0] + b0));
                    atomicAdd(&out[(size_t)tok * D_DIM + col + 1], w * (c[mi][ni][h * 2 + 1] + b1));
                }
            }
        }
    }
}

// ---------------------------------------------------------------------------
extern "C" void kernel_launch(void* const* d_in, const int* in_sizes, int n_in,
                              void* d_out, int out_size) {
    const float* states = (const float*)d_in[0];
    const float* Wg     = (const float*)d_in[1];
    const float* Win    = (const float*)d_in[2];
    const float* bin    = (const float*)d_in[3];
    const float* Wsc    = (const float*)d_in[4];
    const float* bsc    = (const float*)d_in[5];
    const float* Wout   = (const float*)d_in[6];
    const float* bout   = (const float*)d_in[7];
    float* out = (float*)d_out;

    cudaFuncSetAttribute(gemm1_kernel, cudaFuncAttributeMaxDynamicSharedMemorySize, SMEM1);
    cudaFuncSetAttribute(gemm2_kernel, cudaFuncAttributeMaxDynamicSharedMemorySize, SMEM2);

    prep_kernel<<<PREP_TOTAL, 256>>>(Win, Wsc, Wout, states);
    router_kernel<<<N_TOK / 8, 256>>>(states, Wg, out, out_size / 4);
    scatter_kernel<<<1, 256>>>();
    gemm1_kernel<<<dim3(F_DIM / 64, MAXTILES), 512, SMEM1>>>(bin, bsc);
    gemm2_kernel<<<dim3(D_DIM / 64, MAXTILES), 512, SMEM2>>>(bout, out);
}